// round 3
// baseline (speedup 1.0000x reference)
#include <cuda_runtime.h>
#include <cuda_bf16.h>
#include <math.h>
#include <stdint.h>

#define DIM    1024
#define HD     128
#define FF     4096
#define VOC    2048
#define NLM    15
#define NLAYER 5
#define EPSF   1e-6f

// ---------------- scratch ----------------
__device__ float g_h[2 * DIM];
__device__ float g_qkv[6 * DIM];   // q[2][1024] | k[2][1024] | v[2][1024]
__device__ float g_gu[4 * FF];     // gate[2][4096] | up[2][4096]

// ---------------- dynamic smem layout ----------------
// [0,16)    two mbarriers
// [16,48)   sbuf (8 floats)
// [48,64)   attn scalars
// [64,1088) xs (128 x float2)
// [2048, 2048+65536)  2 weight stages (32 rows x 1KB)
// [67584, 75776)      racc (2 x 256 float4)
#define SM_TOTAL 75776
#define ST_OFF   2048
#define RACC_OFF 67584
#define STAGE_BYTES 32768

// ---------------- PTX helpers ----------------
__device__ __forceinline__ uint32_t s2u(const void* p) {
    uint32_t a;
    asm("{ .reg .u64 t; cvta.to.shared.u64 t, %1; cvt.u32.u64 %0, t; }"
        : "=r"(a) : "l"(p));
    return a;
}
#define MB_INIT(mbar, cnt) \
    asm volatile("mbarrier.init.shared.b64 [%0], %1;" :: "r"(mbar), "r"(cnt) : "memory")
#define MB_EXPECT(mbar, bytes) \
    asm volatile("mbarrier.arrive.expect_tx.shared.b64 _, [%0], %1;" :: "r"(mbar), "r"(bytes) : "memory")
#define MB_WAIT(mbar, ph) do {                                                   \
    asm volatile("{\n\t.reg .pred P1;\n\t"                                       \
        "W_%=:\n\t"                                                              \
        "mbarrier.try_wait.parity.acquire.cta.shared::cta.b64 P1, [%0], %1, 0x989680;\n\t" \
        "@P1 bra.uni D_%=;\n\t"                                                  \
        "bra.uni W_%=;\n\t"                                                      \
        "D_%=:\n\t}"                                                             \
        :: "r"(mbar), "r"(ph) : "memory");                                       \
} while (0)
__device__ __forceinline__ void bulk_g2s(uint32_t dst, const void* src,
                                         uint32_t bytes, uint32_t mbar) {
    asm volatile(
        "cp.async.bulk.shared::cluster.global.mbarrier::complete_tx::bytes "
        "[%0], [%1], %2, [%3];"
        :: "r"(dst), "l"(src), "r"(bytes), "r"(mbar) : "memory");
}

// ---------------- reductions ----------------
__device__ __forceinline__ float wred(float v) {
#pragma unroll
    for (int o = 16; o > 0; o >>= 1) v += __shfl_xor_sync(0xffffffffu, v, o);
    return v;
}
__device__ __forceinline__ float bred256(float v, float* sbuf) {
    int tid = threadIdx.x;
#pragma unroll
    for (int o = 16; o > 0; o >>= 1) v += __shfl_down_sync(0xffffffffu, v, o);
    if ((tid & 31) == 0) sbuf[tid >> 5] = v;
    __syncthreads();
    if (tid < 32) {
        float r = (tid < 8) ? sbuf[tid] : 0.f;
#pragma unroll
        for (int o = 4; o > 0; o >>= 1) r += __shfl_down_sync(0xffffffffu, r, o);
        if (tid == 0) sbuf[0] = r;
    }
    __syncthreads();
    float r = sbuf[0];
    __syncthreads();
    return r;
}

// ---------------- pipeline pieces ----------------
// begin: init barriers, prefetch up to 2 stages
__device__ __forceinline__ void pipe_begin(char* sm, const float* Wt,
                                           size_t rowStrideF, int nst) {
    int tid = threadIdx.x;
    uint32_t mb = s2u(sm);
    if (tid == 0) { MB_INIT(mb, 1); MB_INIT(mb + 8, 1); }
    __syncthreads();
    if (tid == 0) {
        uint32_t st = s2u(sm + ST_OFF);
        int pf = nst < 2 ? nst : 2;
        for (int s = 0; s < pf; s++) {
            MB_EXPECT(mb + 8 * s, STAGE_BYTES);
            for (int r = 0; r < 32; r++)
                bulk_g2s(st + s * STAGE_BYTES + r * 1024,
                         Wt + (size_t)(s * 32 + r) * rowStrideF, 1024,
                         mb + 8 * s);
        }
    }
}

// run: consume nst stages, 2 tokens
__device__ __forceinline__ void pipe_run2(char* sm, const float* Wt,
                                          size_t rowStrideF, int nst,
                                          float4& A0, float4& A1) {
    int tid = threadIdx.x, f4c = tid & 63, grp = tid >> 6;
    uint32_t mb = s2u(sm);
    uint32_t st = s2u(sm + ST_OFF);
    const float4* stf = (const float4*)(sm + ST_OFF);
    const float2* xs = (const float2*)(sm + 64);
    for (int it = 0; it < nst; it++) {
        int b = it & 1;
        MB_WAIT(mb + 8 * b, (it >> 1) & 1);
        const float4* ws = stf + b * 2048;
#pragma unroll
        for (int r = 0; r < 8; r++) {
            int row = grp * 8 + r;
            float4 w = ws[row * 64 + f4c];
            float2 x = xs[it * 32 + row];
            A0.x = fmaf(w.x, x.x, A0.x); A0.y = fmaf(w.y, x.x, A0.y);
            A0.z = fmaf(w.z, x.x, A0.z); A0.w = fmaf(w.w, x.x, A0.w);
            A1.x = fmaf(w.x, x.y, A1.x); A1.y = fmaf(w.y, x.y, A1.y);
            A1.z = fmaf(w.z, x.y, A1.z); A1.w = fmaf(w.w, x.y, A1.w);
        }
        if (it + 2 < nst) {
            __syncthreads();
            if (tid == 0) {
                MB_EXPECT(mb + 8 * b, STAGE_BYTES);
                for (int r = 0; r < 32; r++)
                    bulk_g2s(st + b * STAGE_BYTES + r * 1024,
                             Wt + (size_t)((it + 2) * 32 + r) * rowStrideF,
                             1024, mb + 8 * b);
            }
        }
    }
}

__device__ __forceinline__ void reduce_atomic2(char* sm, float4 A0, float4 A1,
                                               float* out0, float* out1) {
    float4* r0 = (float4*)(sm + RACC_OFF);
    float4* r1 = r0 + 256;
    int tid = threadIdx.x, f4c = tid & 63, grp = tid >> 6;
    r0[grp * 64 + f4c] = A0;
    r1[grp * 64 + f4c] = A1;
    __syncthreads();
    if (tid < 64) {
        float4 t0 = r0[tid], t1 = r1[tid];
#pragma unroll
        for (int g = 1; g < 4; g++) {
            float4 a = r0[g * 64 + tid], b = r1[g * 64 + tid];
            t0.x += a.x; t0.y += a.y; t0.z += a.z; t0.w += a.w;
            t1.x += b.x; t1.y += b.y; t1.z += b.z; t1.w += b.w;
        }
        int c = tid * 4;
        atomicAdd(&out0[c + 0], t0.x); atomicAdd(&out0[c + 1], t0.y);
        atomicAdd(&out0[c + 2], t0.z); atomicAdd(&out0[c + 3], t0.w);
        atomicAdd(&out1[c + 0], t1.x); atomicAdd(&out1[c + 1], t1.y);
        atomicAdd(&out1[c + 2], t1.z); atomicAdd(&out1[c + 3], t1.w);
    }
}

// rmsnorm of g_h into xs rows [rbase, rbase+R)
__device__ __forceinline__ void norm_xs(const float* lnw, int rbase, int R,
                                        char* sm) {
    float* sbuf = (float*)(sm + 16);
    float2* xs = (float2*)(sm + 64);
    int tid = threadIdx.x;
    float s0 = 0.f, s1 = 0.f;
#pragma unroll
    for (int i = 0; i < 4; i++) {
        int idx = tid + i * 256;
        float a = g_h[idx], b = g_h[DIM + idx];
        s0 += a * a; s1 += b * b;
    }
    s0 = bred256(s0, sbuf);
    s1 = bred256(s1, sbuf);
    float r0 = rsqrtf(s0 * (1.f / DIM) + EPSF);
    float r1 = rsqrtf(s1 * (1.f / DIM) + EPSF);
    for (int i = tid; i < R; i += 256) {
        int idx = rbase + i;
        float wl = lnw[idx];
        xs[i] = make_float2(g_h[idx] * r0 * wl, g_h[DIM + idx] * r1 * wl);
    }
    __syncthreads();
}

// ---------------- embed ----------------
__global__ void k_embed(const float* __restrict__ past,
                        const float* __restrict__ emb,
                        const int* __restrict__ tok,
                        float* __restrict__ logits) {
    int t = tok[0];
    int gt = blockIdx.x * blockDim.x + threadIdx.x;
    int stride = gridDim.x * blockDim.x;
    for (int i = gt; i < DIM; i += stride) {
        g_h[i] = past[i];
        g_h[DIM + i] = emb[(size_t)t * DIM + i];
    }
    for (int i = gt; i < 6 * DIM; i += stride) g_qkv[i] = 0.f;
    for (int i = gt; i < NLM * VOC; i += stride) logits[i] = 0.f;
}

// ---------------- QKV: grid 192 (3 mats x 4 coltiles x 16 rowchunks) ------
__global__ void __launch_bounds__(256) k_qkv(const float* __restrict__ Wq,
                                             const float* __restrict__ Wk,
                                             const float* __restrict__ Wv,
                                             const float* __restrict__ lnw) {
    extern __shared__ char sm[];
    int bx = blockIdx.x;
    int mat = bx >> 6, colt = (bx >> 4) & 3, rch = bx & 15;
    const float* W = (mat == 0) ? Wq : (mat == 1 ? Wk : Wv);
    const float* Wt = W + (size_t)(rch * 64) * DIM + colt * 256;
    pipe_begin(sm, Wt, DIM, 2);
    norm_xs(lnw, rch * 64, 64, sm);
    float4 A0 = {0, 0, 0, 0}, A1 = {0, 0, 0, 0};
    pipe_run2(sm, Wt, DIM, 2, A0, A1);
    float* out0 = g_qkv + mat * 2048 + colt * 256;
    reduce_atomic2(sm, A0, A1, out0, out0 + DIM);
}

// ---------------- Wo + attention: grid 128 (4 coltiles x 32 rowchunks) ----
__global__ void __launch_bounds__(256) k_wo_attn(const float* __restrict__ Wo,
                                                 const float* __restrict__ qnw,
                                                 const float* __restrict__ knw,
                                                 float* __restrict__ kv) {
    extern __shared__ char sm[];
    int bx = blockIdx.x;
    int colt = bx & 3, rch = bx >> 2;
    int hh = rch >> 2;
    int tid = threadIdx.x;
    const float* Wt = Wo + (size_t)(rch * 32) * DIM + colt * 256;
    pipe_begin(sm, Wt, DIM, 1);

    // zero g_gu for this layer's gateup (128 blocks x 256 covers 16384... guard)
    {
        int idx = bx * 256 + tid;
        if (idx < 4 * FF) g_gu[idx] = 0.f;
    }

    float* sc = (float*)(sm + 48);  // e0, e1, inv
    float2* xs = (float2*)(sm + 64);

    if (tid < 32) {
        int l = tid;
        float4 q1 = ((const float4*)(g_qkv + DIM + hh * HD))[l];
        float4 k0 = ((const float4*)(g_qkv + 2048 + hh * HD))[l];
        float4 k1 = ((const float4*)(g_qkv + 2048 + DIM + hh * HD))[l];
        float nq1 = wred(q1.x * q1.x + q1.y * q1.y + q1.z * q1.z + q1.w * q1.w);
        float nk0 = wred(k0.x * k0.x + k0.y * k0.y + k0.z * k0.z + k0.w * k0.w);
        float nk1 = wred(k1.x * k1.x + k1.y * k1.y + k1.z * k1.z + k1.w * k1.w);
        float rq1 = rsqrtf(nq1 * (1.f / HD) + EPSF);
        float rk0 = rsqrtf(nk0 * (1.f / HD) + EPSF);
        float rk1 = rsqrtf(nk1 * (1.f / HD) + EPSF);
        float4 qn4 = ((const float4*)qnw)[l];
        float4 kn4 = ((const float4*)knw)[l];
        q1.x *= rq1 * qn4.x; q1.y *= rq1 * qn4.y; q1.z *= rq1 * qn4.z; q1.w *= rq1 * qn4.w;
        k0.x *= rk0 * kn4.x; k0.y *= rk0 * kn4.y; k0.z *= rk0 * kn4.z; k0.w *= rk0 * kn4.w;
        k1.x *= rk1 * kn4.x; k1.y *= rk1 * kn4.y; k1.z *= rk1 * kn4.z; k1.w *= rk1 * kn4.w;
        int jb = 4 * (l & 15);
        const float C = 9.210340371976184f / 64.f;
        float a0 = expf(-(float)(jb + 0) * C);
        float a1 = expf(-(float)(jb + 1) * C);
        float a2 = expf(-(float)(jb + 2) * C);
        float a3 = expf(-(float)(jb + 3) * C);
        float csx = cosf(a0), snx = sinf(a0);
        float csy = cosf(a1), sny = sinf(a1);
        float csz = cosf(a2), snz = sinf(a2);
        float csw = cosf(a3), snw = sinf(a3);
        float sgn = (l < 16) ? -1.f : 1.f;
        float4 pq, pk;
        pq.x = __shfl_xor_sync(0xffffffffu, q1.x, 16);
        pq.y = __shfl_xor_sync(0xffffffffu, q1.y, 16);
        pq.z = __shfl_xor_sync(0xffffffffu, q1.z, 16);
        pq.w = __shfl_xor_sync(0xffffffffu, q1.w, 16);
        pk.x = __shfl_xor_sync(0xffffffffu, k1.x, 16);
        pk.y = __shfl_xor_sync(0xffffffffu, k1.y, 16);
        pk.z = __shfl_xor_sync(0xffffffffu, k1.z, 16);
        pk.w = __shfl_xor_sync(0xffffffffu, k1.w, 16);
        q1.x = q1.x * csx + sgn * pq.x * snx;
        q1.y = q1.y * csy + sgn * pq.y * sny;
        q1.z = q1.z * csz + sgn * pq.z * snz;
        q1.w = q1.w * csw + sgn * pq.w * snw;
        k1.x = k1.x * csx + sgn * pk.x * snx;
        k1.y = k1.y * csy + sgn * pk.y * sny;
        k1.z = k1.z * csz + sgn * pk.z * snz;
        k1.w = k1.w * csw + sgn * pk.w * snw;
        float d10 = wred(q1.x * k0.x + q1.y * k0.y + q1.z * k0.z + q1.w * k0.w);
        float d11 = wred(q1.x * k1.x + q1.y * k1.y + q1.z * k1.z + q1.w * k1.w);
        const float scale = 0.08838834764831845f;
        float s10 = d10 * scale, s11 = d11 * scale;
        float m = fmaxf(s10, s11);
        float e0 = expf(s10 - m), e1 = expf(s11 - m);
        float inv = 1.f / (e0 + e1);
        if (l == 0) { sc[0] = e0; sc[1] = e1; sc[2] = inv; }
        if (colt == 0 && (rch & 3) == 0) {
            float4 v0 = ((const float4*)(g_qkv + 4096 + hh * HD))[l];
            float4 v1 = ((const float4*)(g_qkv + 4096 + DIM + hh * HD))[l];
            ((float4*)(kv + hh * 256))[l] = k0;
            ((float4*)(kv + hh * 256 + HD))[l] = k1;
            ((float4*)(kv + 2048 + hh * 256))[l] = v0;
            ((float4*)(kv + 2048 + hh * 256 + HD))[l] = v1;
        }
    }
    __syncthreads();
    if (tid < 32) {
        int dim = rch * 32 + tid;
        float v0 = g_qkv[4096 + dim];
        float v1 = g_qkv[4096 + DIM + dim];
        xs[tid] = make_float2(v0, (sc[0] * v0 + sc[1] * v1) * sc[2]);
    }
    __syncthreads();

    float4 A0 = {0, 0, 0, 0}, A1 = {0, 0, 0, 0};
    pipe_run2(sm, Wt, DIM, 1, A0, A1);
    float* out0 = g_h + colt * 256;
    reduce_atomic2(sm, A0, A1, out0, out0 + DIM);
}

// ---------------- gate/up: grid 256 (2 x 16 coltiles x 8 rowchunks) -------
__global__ void __launch_bounds__(256) k_gateup(const float* __restrict__ Wg,
                                                const float* __restrict__ Wu,
                                                const float* __restrict__ lnw) {
    extern __shared__ char sm[];
    int bx = blockIdx.x;
    int mat = bx >> 7, colt = (bx >> 3) & 15, rch = bx & 7;
    const float* W = mat ? Wu : Wg;
    const float* Wt = W + (size_t)(rch * 128) * FF + colt * 256;
    pipe_begin(sm, Wt, FF, 4);
    norm_xs(lnw, rch * 128, 128, sm);
    float4 A0 = {0, 0, 0, 0}, A1 = {0, 0, 0, 0};
    pipe_run2(sm, Wt, FF, 4, A0, A1);
    float* out0 = g_gu + mat * 8192 + colt * 256;
    reduce_atomic2(sm, A0, A1, out0, out0 + FF);
}

// ---------------- down: grid 128 (4 coltiles x 32 rowchunks) --------------
__global__ void __launch_bounds__(256) k_down(const float* __restrict__ Wd) {
    extern __shared__ char sm[];
    int bx = blockIdx.x;
    int colt = bx >> 5, rch = bx & 31;
    int tid = threadIdx.x;
    const float* Wt = Wd + (size_t)(rch * 128) * DIM + colt * 256;
    pipe_begin(sm, Wt, DIM, 4);

    if (bx < 24) g_qkv[bx * 256 + tid] = 0.f;  // zero for next layer

    float2* xs = (float2*)(sm + 64);
    if (tid < 128) {
        int idx = rch * 128 + tid;
        float g0 = g_gu[idx],        g1 = g_gu[FF + idx];
        float u0 = g_gu[8192 + idx], u1 = g_gu[8192 + FF + idx];
        xs[tid] = make_float2(g0 / (1.f + expf(-g0)) * u0,
                              g1 / (1.f + expf(-g1)) * u1);
    }
    __syncthreads();

    float4 A0 = {0, 0, 0, 0}, A1 = {0, 0, 0, 0};
    pipe_run2(sm, Wt, DIM, 4, A0, A1);
    float* out0 = g_h + colt * 256;
    reduce_atomic2(sm, A0, A1, out0, out0 + DIM);
}

// ---------------- lm heads: grid 960 (15 x 8 coltiles x 8 rowchunks) ------
__global__ void __launch_bounds__(256) k_lm(const float* __restrict__ lm,
                                            const float* __restrict__ fnw,
                                            float* __restrict__ logits) {
    extern __shared__ char sm[];
    int bx = blockIdx.x;
    int mat = bx >> 6, colt = (bx >> 3) & 7, rch = bx & 7;
    int tid = threadIdx.x;
    const float* Wt = lm + (size_t)mat * DIM * VOC + (size_t)(rch * 128) * VOC +
                      colt * 256;
    pipe_begin(sm, Wt, VOC, 4);

    float* sbuf = (float*)(sm + 16);
    float2* xs = (float2*)(sm + 64);
    float s = 0.f;
#pragma unroll
    for (int i = 0; i < 4; i++) {
        float v = g_h[DIM + tid + i * 256];
        s += v * v;
    }
    s = bred256(s, sbuf);
    float r = rsqrtf(s * (1.f / DIM) + EPSF);
    if (tid < 128) {
        int idx = rch * 128 + tid;
        xs[tid] = make_float2(g_h[DIM + idx] * r * fnw[idx], 0.f);
    }
    __syncthreads();

    float4 A0 = {0, 0, 0, 0}, A1 = {0, 0, 0, 0};
    pipe_run2(sm, Wt, VOC, 4, A0, A1);

    float4* r0 = (float4*)(sm + RACC_OFF);
    int f4c = tid & 63, grp = tid >> 6;
    r0[grp * 64 + f4c] = A0;
    __syncthreads();
    if (tid < 64) {
        float4 t0 = r0[tid];
#pragma unroll
        for (int g = 1; g < 4; g++) {
            float4 a = r0[g * 64 + tid];
            t0.x += a.x; t0.y += a.y; t0.z += a.z; t0.w += a.w;
        }
        float* out = logits + (size_t)mat * VOC + colt * 256 + tid * 4;
        atomicAdd(&out[0], t0.x); atomicAdd(&out[1], t0.y);
        atomicAdd(&out[2], t0.z); atomicAdd(&out[3], t0.w);
    }
}

// ---------------- host launcher ----------------
extern "C" void kernel_launch(void* const* d_in, const int* in_sizes, int n_in,
                              void* d_out, int out_size) {
    const float *past, *emb, *Wq, *Wk, *Wv, *Wo, *qn, *kn, *ln1, *ln2, *Wg, *Wu,
        *Wd, *fn, *lm;
    const int* tok;
    if (in_sizes[1] == 1) {
        past = (const float*)d_in[0];
        tok  = (const int*)d_in[1];
        emb  = (const float*)d_in[2];
        Wq = (const float*)d_in[3];  Wk = (const float*)d_in[4];
        Wv = (const float*)d_in[5];  Wo = (const float*)d_in[6];
        qn = (const float*)d_in[7];  kn = (const float*)d_in[8];
        ln1 = (const float*)d_in[9]; ln2 = (const float*)d_in[10];
        Wg = (const float*)d_in[11]; Wu = (const float*)d_in[12];
        Wd = (const float*)d_in[13]; fn = (const float*)d_in[14];
        lm = (const float*)d_in[15];
    } else {
        past = (const float*)d_in[0];
        emb  = (const float*)d_in[1];
        Wq = (const float*)d_in[2];  Wk = (const float*)d_in[3];
        Wv = (const float*)d_in[4];  Wo = (const float*)d_in[5];
        qn = (const float*)d_in[6];  kn = (const float*)d_in[7];
        ln1 = (const float*)d_in[8]; ln2 = (const float*)d_in[9];
        Wg = (const float*)d_in[10]; Wu = (const float*)d_in[11];
        Wd = (const float*)d_in[12]; fn = (const float*)d_in[13];
        lm = (const float*)d_in[14];
        tok = (const int*)d_in[15];
    }

    static bool attr_done = false;
    if (!attr_done) {
        cudaFuncSetAttribute(k_qkv, cudaFuncAttributeMaxDynamicSharedMemorySize, SM_TOTAL);
        cudaFuncSetAttribute(k_wo_attn, cudaFuncAttributeMaxDynamicSharedMemorySize, SM_TOTAL);
        cudaFuncSetAttribute(k_gateup, cudaFuncAttributeMaxDynamicSharedMemorySize, SM_TOTAL);
        cudaFuncSetAttribute(k_down, cudaFuncAttributeMaxDynamicSharedMemorySize, SM_TOTAL);
        cudaFuncSetAttribute(k_lm, cudaFuncAttributeMaxDynamicSharedMemorySize, SM_TOTAL);
        attr_done = true;
    }

    float* out = (float*)d_out;
    float* logits = out;            // [15][2048]
    float* kvc = out + NLM * VOC;   // [10][8][2][128]

    k_embed<<<32, 256>>>(past, emb, tok, logits);

    for (int l = 0; l < NLAYER; l++) {
        size_t offA = (size_t)l * DIM * DIM;
        size_t offF = (size_t)l * DIM * FF;
        k_qkv<<<192, 256, SM_TOTAL>>>(Wq + offA, Wk + offA, Wv + offA, ln1 + l * DIM);
        k_wo_attn<<<128, 256, SM_TOTAL>>>(Wo + offA, qn + l * HD, kn + l * HD,
                                          kvc + (size_t)l * 4096);
        k_gateup<<<256, 256, SM_TOTAL>>>(Wg + offF, Wu + offF, ln2 + l * DIM);
        k_down<<<128, 256, SM_TOTAL>>>(Wd + offF);
    }

    k_lm<<<960, 256, SM_TOTAL>>>(lm, fn, logits);
    (void)n_in; (void)out_size;
}

// round 4
// speedup vs baseline: 1.1873x; 1.1873x over previous
#include <cuda_runtime.h>
#include <cuda_bf16.h>
#include <math.h>
#include <stdint.h>

#define DIM    1024
#define HD     128
#define FF     4096
#define VOC    2048
#define NLM    15
#define NLAYER 5
#define EPSF   1e-6f

#define NBUF         3
#define STAGE_BYTES  32768
#define STAGE_FLOATS 8192
#define ST_OFF       2048
#define SM_TOTAL     (ST_OFF + NBUF * STAGE_BYTES)   // 100352

// ---------------- scratch ----------------
__device__ float g_h[2 * DIM];
__device__ float g_qkv[6 * DIM];   // q[2][1024] | k[2][1024] | v[2][1024]
__device__ float g_gu[4 * FF];     // gate[2][4096] | up[2][4096]

// ---------------- PTX helpers ----------------
__device__ __forceinline__ uint32_t s2u(const void* p) {
    uint32_t a;
    asm("{ .reg .u64 t; cvta.to.shared.u64 t, %1; cvt.u32.u64 %0, t; }"
        : "=r"(a) : "l"(p));
    return a;
}
#define MB_INIT(mbar, cnt) \
    asm volatile("mbarrier.init.shared.b64 [%0], %1;" :: "r"(mbar), "r"(cnt) : "memory")
#define MB_EXPECT(mbar, bytes) \
    asm volatile("mbarrier.arrive.expect_tx.shared.b64 _, [%0], %1;" :: "r"(mbar), "r"(bytes) : "memory")
#define MB_WAIT(mbar, ph) do {                                                   \
    asm volatile("{\n\t.reg .pred P1;\n\t"                                       \
        "W_%=:\n\t"                                                              \
        "mbarrier.try_wait.parity.acquire.cta.shared::cta.b64 P1, [%0], %1, 0x989680;\n\t" \
        "@P1 bra.uni D_%=;\n\t"                                                  \
        "bra.uni W_%=;\n\t"                                                      \
        "D_%=:\n\t}"                                                             \
        :: "r"(mbar), "r"(ph) : "memory");                                       \
} while (0)
__device__ __forceinline__ void bulk_g2s(uint32_t dst, const void* src,
                                         uint32_t bytes, uint32_t mbar) {
    asm volatile(
        "cp.async.bulk.shared::cluster.global.mbarrier::complete_tx::bytes "
        "[%0], [%1], %2, [%3];"
        :: "r"(dst), "l"(src), "r"(bytes), "r"(mbar) : "memory");
}
__device__ __forceinline__ void red2(float* p, float a, float b) {
    asm volatile("red.global.add.v2.f32 [%0], {%1, %2};"
                 :: "l"(p), "f"(a), "f"(b) : "memory");
}
__device__ __forceinline__ void red4(float* p, float4 v) {
    asm volatile("red.global.add.v4.f32 [%0], {%1, %2, %3, %4};"
                 :: "l"(p), "f"(v.x), "f"(v.y), "f"(v.z), "f"(v.w) : "memory");
}

// ---------------- reductions ----------------
__device__ __forceinline__ float wred(float v) {
#pragma unroll
    for (int o = 16; o > 0; o >>= 1) v += __shfl_xor_sync(0xffffffffu, v, o);
    return v;
}
// 512-thread block reduce
__device__ __forceinline__ float bred512(float v, float* sbuf) {
    int tid = threadIdx.x;
#pragma unroll
    for (int o = 16; o > 0; o >>= 1) v += __shfl_down_sync(0xffffffffu, v, o);
    if ((tid & 31) == 0) sbuf[tid >> 5] = v;
    __syncthreads();
    if (tid < 32) {
        float r = (tid < 16) ? sbuf[tid] : 0.f;
#pragma unroll
        for (int o = 8; o > 0; o >>= 1) r += __shfl_down_sync(0xffffffffu, r, o);
        if (tid == 0) sbuf[0] = r;
    }
    __syncthreads();
    float r = sbuf[0];
    __syncthreads();
    return r;
}

// ---------------- pipeline ----------------
__device__ __forceinline__ void pipe_begin(char* sm, const float* Wt, int nst) {
    int tid = threadIdx.x;
    uint32_t mb = s2u(sm);
    if (tid == 0) {
#pragma unroll
        for (int s = 0; s < NBUF; s++) MB_INIT(mb + 8 * s, 1);
    }
    __syncthreads();
    if (tid == 0) {
        uint32_t st = s2u(sm + ST_OFF);
        int pf = nst < NBUF ? nst : NBUF;
        for (int s = 0; s < pf; s++) {
            MB_EXPECT(mb + 8 * s, STAGE_BYTES);
            bulk_g2s(st + s * STAGE_BYTES, Wt + (size_t)s * STAGE_FLOATS,
                     STAGE_BYTES, mb + 8 * s);
        }
    }
}

template <typename F>
__device__ __forceinline__ void pipe_run(char* sm, const float* Wt, int nst, F f) {
    int tid = threadIdx.x;
    uint32_t mb = s2u(sm);
    uint32_t st = s2u(sm + ST_OFF);
    int slot = 0, ph = 0;
    for (int it = 0; it < nst; it++) {
        MB_WAIT(mb + 8 * slot, ph);
        f(it, (const float*)(sm + ST_OFF + slot * STAGE_BYTES));
        __syncthreads();
        if (it + NBUF < nst && tid == 0) {
            MB_EXPECT(mb + 8 * slot, STAGE_BYTES);
            bulk_g2s(st + slot * STAGE_BYTES,
                     Wt + (size_t)(it + NBUF) * STAGE_FLOATS, STAGE_BYTES,
                     mb + 8 * slot);
        }
        if (++slot == NBUF) { slot = 0; ph ^= 1; }
    }
}

// rmsnorm of g_h rows [rbase, rbase+R) into xs (float2 per row)
__device__ __forceinline__ void norm_xs(const float* lnw, int rbase, int R,
                                        char* sm) {
    float* sbuf = (float*)(sm + ST_OFF - 128);  // 16 floats scratch
    float2* xs = (float2*)(sm + 64);
    int tid = threadIdx.x;
    float s0 = 0.f, s1 = 0.f;
#pragma unroll
    for (int i = 0; i < 2; i++) {
        int idx = tid + i * 512;
        float a = g_h[idx], b = g_h[DIM + idx];
        s0 += a * a; s1 += b * b;
    }
    s0 = bred512(s0, sbuf);
    s1 = bred512(s1, sbuf);
    float r0 = rsqrtf(s0 * (1.f / DIM) + EPSF);
    float r1 = rsqrtf(s1 * (1.f / DIM) + EPSF);
    if (tid < R) {
        int idx = rbase + tid;
        float wl = lnw[idx];
        xs[tid] = make_float2(g_h[idx] * r0 * wl, g_h[DIM + idx] * r1 * wl);
    }
    __syncthreads();
}

// ---------------- embed ----------------
__global__ void k_embed(const float* __restrict__ past,
                        const float* __restrict__ emb,
                        const int* __restrict__ tok,
                        float* __restrict__ logits) {
    int t = tok[0];
    int gt = blockIdx.x * blockDim.x + threadIdx.x;
    int stride = gridDim.x * blockDim.x;
    for (int i = gt; i < DIM; i += stride) {
        g_h[i] = past[i];
        g_h[DIM + i] = emb[(size_t)t * DIM + i];
    }
    for (int i = gt; i < 6 * DIM; i += stride) g_qkv[i] = 0.f;
    for (int i = gt; i < NLM * VOC; i += stride) logits[i] = 0.f;
}

// ---------------- QKV: grid 96 (3 mats x 32 rowchunks of 32 rows) ---------
// width 1024, thread owns 2 cols; stage = 8 rows; nst = 4
__global__ void __launch_bounds__(512) k_qkv(const float* __restrict__ Wq,
                                             const float* __restrict__ Wk,
                                             const float* __restrict__ Wv,
                                             const float* __restrict__ lnw) {
    extern __shared__ char sm[];
    int bx = blockIdx.x;
    int mat = bx >> 5, rch = bx & 31;
    const float* W = (mat == 0) ? Wq : (mat == 1 ? Wk : Wv);
    const float* Wt = W + (size_t)rch * 32 * DIM;
    pipe_begin(sm, Wt, 4);
    norm_xs(lnw, rch * 32, 32, sm);

    const float2* xs = (const float2*)(sm + 64);
    int tid = threadIdx.x;
    float a00 = 0.f, a01 = 0.f, a10 = 0.f, a11 = 0.f;
    pipe_run(sm, Wt, 4, [&](int it, const float* buf) {
        const float2* bw = (const float2*)buf;
#pragma unroll
        for (int r = 0; r < 8; r++) {
            float2 w = bw[r * 512 + tid];
            float2 x = xs[it * 8 + r];
            a00 = fmaf(w.x, x.x, a00); a01 = fmaf(w.y, x.x, a01);
            a10 = fmaf(w.x, x.y, a10); a11 = fmaf(w.y, x.y, a11);
        }
    });
    float* o = g_qkv + mat * 2048;
    red2(o + 2 * tid, a00, a01);
    red2(o + DIM + 2 * tid, a10, a11);
}

// ---------------- Wo + attention: grid 64 (rowchunks of 16 rows) ----------
// width 1024, stage = 8 rows, nst = 2
__global__ void __launch_bounds__(512) k_wo_attn(const float* __restrict__ Wo,
                                                 const float* __restrict__ qnw,
                                                 const float* __restrict__ knw,
                                                 float* __restrict__ kv) {
    extern __shared__ char sm[];
    int bx = blockIdx.x;
    int rch = bx;                 // 0..63, 16 rows each
    int hh = rch >> 3;            // head
    int tid = threadIdx.x;
    const float* Wt = Wo + (size_t)rch * 16 * DIM;
    pipe_begin(sm, Wt, 2);

    // zero g_gu for the upcoming gateup reds (64 x 512 = 32768 >= 16384)
    {
        int idx = bx * 512 + tid;
        if (idx < 4 * FF) g_gu[idx] = 0.f;
    }

    float* sc = (float*)(sm + 48);       // e0, e1, inv
    float2* xs = (float2*)(sm + 64);

    if (tid < 32) {
        int l = tid;
        float4 q1 = ((const float4*)(g_qkv + DIM + hh * HD))[l];
        float4 k0 = ((const float4*)(g_qkv + 2048 + hh * HD))[l];
        float4 k1 = ((const float4*)(g_qkv + 2048 + DIM + hh * HD))[l];
        float nq1 = wred(q1.x * q1.x + q1.y * q1.y + q1.z * q1.z + q1.w * q1.w);
        float nk0 = wred(k0.x * k0.x + k0.y * k0.y + k0.z * k0.z + k0.w * k0.w);
        float nk1 = wred(k1.x * k1.x + k1.y * k1.y + k1.z * k1.z + k1.w * k1.w);
        float rq1 = rsqrtf(nq1 * (1.f / HD) + EPSF);
        float rk0 = rsqrtf(nk0 * (1.f / HD) + EPSF);
        float rk1 = rsqrtf(nk1 * (1.f / HD) + EPSF);
        float4 qn4 = ((const float4*)qnw)[l];
        float4 kn4 = ((const float4*)knw)[l];
        q1.x *= rq1 * qn4.x; q1.y *= rq1 * qn4.y; q1.z *= rq1 * qn4.z; q1.w *= rq1 * qn4.w;
        k0.x *= rk0 * kn4.x; k0.y *= rk0 * kn4.y; k0.z *= rk0 * kn4.z; k0.w *= rk0 * kn4.w;
        k1.x *= rk1 * kn4.x; k1.y *= rk1 * kn4.y; k1.z *= rk1 * kn4.z; k1.w *= rk1 * kn4.w;
        int jb = 4 * (l & 15);
        const float C = 9.210340371976184f / 64.f;
        float an0 = expf(-(float)(jb + 0) * C);
        float an1 = expf(-(float)(jb + 1) * C);
        float an2 = expf(-(float)(jb + 2) * C);
        float an3 = expf(-(float)(jb + 3) * C);
        float csx = cosf(an0), snx = sinf(an0);
        float csy = cosf(an1), sny = sinf(an1);
        float csz = cosf(an2), snz = sinf(an2);
        float csw = cosf(an3), snw = sinf(an3);
        float sgn = (l < 16) ? -1.f : 1.f;
        float4 pq, pk;
        pq.x = __shfl_xor_sync(0xffffffffu, q1.x, 16);
        pq.y = __shfl_xor_sync(0xffffffffu, q1.y, 16);
        pq.z = __shfl_xor_sync(0xffffffffu, q1.z, 16);
        pq.w = __shfl_xor_sync(0xffffffffu, q1.w, 16);
        pk.x = __shfl_xor_sync(0xffffffffu, k1.x, 16);
        pk.y = __shfl_xor_sync(0xffffffffu, k1.y, 16);
        pk.z = __shfl_xor_sync(0xffffffffu, k1.z, 16);
        pk.w = __shfl_xor_sync(0xffffffffu, k1.w, 16);
        q1.x = q1.x * csx + sgn * pq.x * snx;
        q1.y = q1.y * csy + sgn * pq.y * sny;
        q1.z = q1.z * csz + sgn * pq.z * snz;
        q1.w = q1.w * csw + sgn * pq.w * snw;
        k1.x = k1.x * csx + sgn * pk.x * snx;
        k1.y = k1.y * csy + sgn * pk.y * sny;
        k1.z = k1.z * csz + sgn * pk.z * snz;
        k1.w = k1.w * csw + sgn * pk.w * snw;
        float d10 = wred(q1.x * k0.x + q1.y * k0.y + q1.z * k0.z + q1.w * k0.w);
        float d11 = wred(q1.x * k1.x + q1.y * k1.y + q1.z * k1.z + q1.w * k1.w);
        const float scale = 0.08838834764831845f;
        float s10 = d10 * scale, s11 = d11 * scale;
        float m = fmaxf(s10, s11);
        float e0 = expf(s10 - m), e1 = expf(s11 - m);
        float inv = 1.f / (e0 + e1);
        if (l == 0) { sc[0] = e0; sc[1] = e1; sc[2] = inv; }
        if ((rch & 7) == 0) {
            float4 v0 = ((const float4*)(g_qkv + 4096 + hh * HD))[l];
            float4 v1 = ((const float4*)(g_qkv + 4096 + DIM + hh * HD))[l];
            ((float4*)(kv + hh * 256))[l] = k0;
            ((float4*)(kv + hh * 256 + HD))[l] = k1;
            ((float4*)(kv + 2048 + hh * 256))[l] = v0;
            ((float4*)(kv + 2048 + hh * 256 + HD))[l] = v1;
        }
    }
    __syncthreads();
    if (tid < 16) {
        int dim = rch * 16 + tid;
        float v0 = g_qkv[4096 + dim];
        float v1 = g_qkv[4096 + DIM + dim];
        xs[tid] = make_float2(v0, (sc[0] * v0 + sc[1] * v1) * sc[2]);
    }
    __syncthreads();

    float a00 = 0.f, a01 = 0.f, a10 = 0.f, a11 = 0.f;
    pipe_run(sm, Wt, 2, [&](int it, const float* buf) {
        const float2* bw = (const float2*)buf;
#pragma unroll
        for (int r = 0; r < 8; r++) {
            float2 w = bw[r * 512 + tid];
            float2 x = xs[it * 8 + r];
            a00 = fmaf(w.x, x.x, a00); a01 = fmaf(w.y, x.x, a01);
            a10 = fmaf(w.x, x.y, a10); a11 = fmaf(w.y, x.y, a11);
        }
    });
    red2(g_h + 2 * tid, a00, a01);
    red2(g_h + DIM + 2 * tid, a10, a11);
}

// ---------------- gate/up: grid 128 (2 mats x 64 rowchunks of 16 rows) ----
// width 4096, thread owns cols [4t,4t+4) and [2048+4t,..); stage = 2 rows; nst = 8
__global__ void __launch_bounds__(512) k_gateup(const float* __restrict__ Wg,
                                                const float* __restrict__ Wu,
                                                const float* __restrict__ lnw) {
    extern __shared__ char sm[];
    int bx = blockIdx.x;
    int mat = bx >> 6, rch = bx & 63;
    const float* W = mat ? Wu : Wg;
    const float* Wt = W + (size_t)rch * 16 * FF;
    pipe_begin(sm, Wt, 8);
    norm_xs(lnw, rch * 16, 16, sm);

    const float2* xs = (const float2*)(sm + 64);
    int tid = threadIdx.x;
    float4 A00 = {0,0,0,0}, A01 = {0,0,0,0}, A10 = {0,0,0,0}, A11 = {0,0,0,0};
    pipe_run(sm, Wt, 8, [&](int it, const float* buf) {
        const float4* b4 = (const float4*)buf;
#pragma unroll
        for (int r = 0; r < 2; r++) {
            float2 x = xs[it * 2 + r];
            float4 w0 = b4[r * 1024 + tid];
            float4 w1 = b4[r * 1024 + 512 + tid];
            A00.x = fmaf(w0.x, x.x, A00.x); A00.y = fmaf(w0.y, x.x, A00.y);
            A00.z = fmaf(w0.z, x.x, A00.z); A00.w = fmaf(w0.w, x.x, A00.w);
            A10.x = fmaf(w0.x, x.y, A10.x); A10.y = fmaf(w0.y, x.y, A10.y);
            A10.z = fmaf(w0.z, x.y, A10.z); A10.w = fmaf(w0.w, x.y, A10.w);
            A01.x = fmaf(w1.x, x.x, A01.x); A01.y = fmaf(w1.y, x.x, A01.y);
            A01.z = fmaf(w1.z, x.x, A01.z); A01.w = fmaf(w1.w, x.x, A01.w);
            A11.x = fmaf(w1.x, x.y, A11.x); A11.y = fmaf(w1.y, x.y, A11.y);
            A11.z = fmaf(w1.z, x.y, A11.z); A11.w = fmaf(w1.w, x.y, A11.w);
        }
    });
    float* o = g_gu + mat * 8192;
    red4(o + 4 * tid, A00);
    red4(o + 2048 + 4 * tid, A01);
    red4(o + FF + 4 * tid, A10);
    red4(o + FF + 2048 + 4 * tid, A11);
}

// ---------------- down: grid 128 (rowchunks of 32 rows) -------------------
// width 1024, stage = 8 rows, nst = 4
__global__ void __launch_bounds__(512) k_down(const float* __restrict__ Wd) {
    extern __shared__ char sm[];
    int bx = blockIdx.x;
    int rch = bx;   // 0..127, 32 rows each
    int tid = threadIdx.x;
    const float* Wt = Wd + (size_t)rch * 32 * DIM;
    pipe_begin(sm, Wt, 4);

    if (bx < 12) g_qkv[bx * 512 + tid] = 0.f;   // zero for next layer

    float2* xs = (float2*)(sm + 64);
    if (tid < 32) {
        int idx = rch * 32 + tid;
        float g0 = g_gu[idx],        g1 = g_gu[FF + idx];
        float u0 = g_gu[8192 + idx], u1 = g_gu[8192 + FF + idx];
        xs[tid] = make_float2(g0 / (1.f + expf(-g0)) * u0,
                              g1 / (1.f + expf(-g1)) * u1);
    }
    __syncthreads();

    float a00 = 0.f, a01 = 0.f, a10 = 0.f, a11 = 0.f;
    pipe_run(sm, Wt, 4, [&](int it, const float* buf) {
        const float2* bw = (const float2*)buf;
#pragma unroll
        for (int r = 0; r < 8; r++) {
            float2 w = bw[r * 512 + tid];
            float2 x = xs[it * 8 + r];
            a00 = fmaf(w.x, x.x, a00); a01 = fmaf(w.y, x.x, a01);
            a10 = fmaf(w.x, x.y, a10); a11 = fmaf(w.y, x.y, a11);
        }
    });
    red2(g_h + 2 * tid, a00, a01);
    red2(g_h + DIM + 2 * tid, a10, a11);
}

// ---------------- lm heads: grid 240 (15 mats x 16 rowchunks of 64 rows) --
// width 2048, thread owns cols [4t,4t+4); stage = 4 rows; nst = 16
__global__ void __launch_bounds__(512) k_lm(const float* __restrict__ lm,
                                            const float* __restrict__ fnw,
                                            float* __restrict__ logits) {
    extern __shared__ char sm[];
    int bx = blockIdx.x;
    int mat = bx >> 4, rch = bx & 15;
    int tid = threadIdx.x;
    const float* Wt = lm + (size_t)mat * DIM * VOC + (size_t)rch * 64 * VOC;
    pipe_begin(sm, Wt, 16);

    float* sbuf = (float*)(sm + ST_OFF - 128);
    float* xs = (float*)(sm + 64);
    float s = 0.f;
#pragma unroll
    for (int i = 0; i < 2; i++) {
        float v = g_h[DIM + tid + i * 512];
        s += v * v;
    }
    s = bred512(s, sbuf);
    float r = rsqrtf(s * (1.f / DIM) + EPSF);
    if (tid < 64) {
        int idx = rch * 64 + tid;
        xs[tid] = g_h[DIM + idx] * r * fnw[idx];
    }
    __syncthreads();

    float4 A = {0, 0, 0, 0};
    pipe_run(sm, Wt, 16, [&](int it, const float* buf) {
        const float4* b4 = (const float4*)buf;
#pragma unroll
        for (int r2 = 0; r2 < 4; r2++) {
            float x = xs[it * 4 + r2];
            float4 w = b4[r2 * 512 + tid];
            A.x = fmaf(w.x, x, A.x); A.y = fmaf(w.y, x, A.y);
            A.z = fmaf(w.z, x, A.z); A.w = fmaf(w.w, x, A.w);
        }
    });
    red4(logits + (size_t)mat * VOC + 4 * tid, A);
}

// ---------------- host launcher ----------------
extern "C" void kernel_launch(void* const* d_in, const int* in_sizes, int n_in,
                              void* d_out, int out_size) {
    const float *past, *emb, *Wq, *Wk, *Wv, *Wo, *qn, *kn, *ln1, *ln2, *Wg, *Wu,
        *Wd, *fn, *lm;
    const int* tok;
    if (in_sizes[1] == 1) {
        past = (const float*)d_in[0];
        tok  = (const int*)d_in[1];
        emb  = (const float*)d_in[2];
        Wq = (const float*)d_in[3];  Wk = (const float*)d_in[4];
        Wv = (const float*)d_in[5];  Wo = (const float*)d_in[6];
        qn = (const float*)d_in[7];  kn = (const float*)d_in[8];
        ln1 = (const float*)d_in[9]; ln2 = (const float*)d_in[10];
        Wg = (const float*)d_in[11]; Wu = (const float*)d_in[12];
        Wd = (const float*)d_in[13]; fn = (const float*)d_in[14];
        lm = (const float*)d_in[15];
    } else {
        past = (const float*)d_in[0];
        emb  = (const float*)d_in[1];
        Wq = (const float*)d_in[2];  Wk = (const float*)d_in[3];
        Wv = (const float*)d_in[4];  Wo = (const float*)d_in[5];
        qn = (const float*)d_in[6];  kn = (const float*)d_in[7];
        ln1 = (const float*)d_in[8]; ln2 = (const float*)d_in[9];
        Wg = (const float*)d_in[10]; Wu = (const float*)d_in[11];
        Wd = (const float*)d_in[12]; fn = (const float*)d_in[13];
        lm = (const float*)d_in[14];
        tok = (const int*)d_in[15];
    }

    static bool attr_done = false;
    if (!attr_done) {
        cudaFuncSetAttribute(k_qkv, cudaFuncAttributeMaxDynamicSharedMemorySize, SM_TOTAL);
        cudaFuncSetAttribute(k_wo_attn, cudaFuncAttributeMaxDynamicSharedMemorySize, SM_TOTAL);
        cudaFuncSetAttribute(k_gateup, cudaFuncAttributeMaxDynamicSharedMemorySize, SM_TOTAL);
        cudaFuncSetAttribute(k_down, cudaFuncAttributeMaxDynamicSharedMemorySize, SM_TOTAL);
        cudaFuncSetAttribute(k_lm, cudaFuncAttributeMaxDynamicSharedMemorySize, SM_TOTAL);
        attr_done = true;
    }

    float* out = (float*)d_out;
    float* logits = out;            // [15][2048]
    float* kvc = out + NLM * VOC;   // [10][8][2][128]

    k_embed<<<32, 256>>>(past, emb, tok, logits);

    for (int l = 0; l < NLAYER; l++) {
        size_t offA = (size_t)l * DIM * DIM;
        size_t offF = (size_t)l * DIM * FF;
        k_qkv<<<96, 512, SM_TOTAL>>>(Wq + offA, Wk + offA, Wv + offA, ln1 + l * DIM);
        k_wo_attn<<<64, 512, SM_TOTAL>>>(Wo + offA, qn + l * HD, kn + l * HD,
                                         kvc + (size_t)l * 4096);
        k_gateup<<<128, 512, SM_TOTAL>>>(Wg + offF, Wu + offF, ln2 + l * DIM);
        k_down<<<128, 512, SM_TOTAL>>>(Wd + offF);
    }

    k_lm<<<240, 512, SM_TOTAL>>>(lm, fn, logits);
    (void)n_in; (void)out_size;
}

// round 5
// speedup vs baseline: 1.2024x; 1.0128x over previous
#include <cuda_runtime.h>
#include <cuda_bf16.h>
#include <math.h>
#include <stdint.h>

#define DIM    1024
#define HD     128
#define FF     4096
#define VOC    2048
#define NLM    15
#define NLAYER 5
#define EPSF   1e-6f
#define NBLK   148
#define NTHR   512

#define NBUF         6
#define STAGE_BYTES  32768
#define STAGE_FLOATS 8192
// smem layout: [0,48) 6 mbarriers | [48,64) attn scalars | [64,4160) xs (4KB)
// [4608,5888) stage table (160 ptrs) | [6400,6464) sbuf | [8192, +6*32K) stages
#define XS_OFF   64
#define TAB_OFF  4608
#define SBUF_OFF 6400
#define ST_OFF   8192
#define SM_TOTAL (ST_OFF + NBUF * STAGE_BYTES)   // 204800

// ---------------- device scratch ----------------
__device__ float g_h[2 * DIM];
__device__ float g_qkv[6 * DIM];   // q[2][1024] | k[2][1024] | v[2][1024]
__device__ float g_gu[4 * FF];     // gate[2][4096] | up[2][4096]
__device__ unsigned g_bar[32];     // zero-initialized; restored at end of run
__device__ unsigned g_fin;

// ---------------- PTX helpers ----------------
__device__ __forceinline__ uint32_t s2u(const void* p) {
    uint32_t a;
    asm("{ .reg .u64 t; cvta.to.shared.u64 t, %1; cvt.u32.u64 %0, t; }"
        : "=r"(a) : "l"(p));
    return a;
}
#define MB_INIT(mbar, cnt) \
    asm volatile("mbarrier.init.shared.b64 [%0], %1;" :: "r"(mbar), "r"(cnt) : "memory")
#define MB_EXPECT(mbar, bytes) \
    asm volatile("mbarrier.arrive.expect_tx.shared.b64 _, [%0], %1;" :: "r"(mbar), "r"(bytes) : "memory")
#define MB_WAIT(mbar, ph) do {                                                   \
    asm volatile("{\n\t.reg .pred P1;\n\t"                                       \
        "W_%=:\n\t"                                                              \
        "mbarrier.try_wait.parity.acquire.cta.shared::cta.b64 P1, [%0], %1, 0x989680;\n\t" \
        "@P1 bra.uni D_%=;\n\t"                                                  \
        "bra.uni W_%=;\n\t"                                                      \
        "D_%=:\n\t}"                                                             \
        :: "r"(mbar), "r"(ph) : "memory");                                       \
} while (0)
__device__ __forceinline__ void bulk_g2s(uint32_t dst, const void* src,
                                         uint32_t bytes, uint32_t mbar) {
    asm volatile(
        "cp.async.bulk.shared::cluster.global.mbarrier::complete_tx::bytes "
        "[%0], [%1], %2, [%3];"
        :: "r"(dst), "l"(src), "r"(bytes), "r"(mbar) : "memory");
}
__device__ __forceinline__ void red2(float* p, float a, float b) {
    asm volatile("red.global.add.v2.f32 [%0], {%1, %2};"
                 :: "l"(p), "f"(a), "f"(b) : "memory");
}
__device__ __forceinline__ void red4(float* p, float4 v) {
    asm volatile("red.global.add.v4.f32 [%0], {%1, %2, %3, %4};"
                 :: "l"(p), "f"(v.x), "f"(v.y), "f"(v.z), "f"(v.w) : "memory");
}
__device__ __forceinline__ float ldcg(const float* p) {
    float v;
    asm volatile("ld.global.cg.f32 %0, [%1];" : "=f"(v) : "l"(p));
    return v;
}
__device__ __forceinline__ float4 ldcg4(const float* p) {
    float4 v;
    asm volatile("ld.global.cg.v4.f32 {%0,%1,%2,%3}, [%4];"
                 : "=f"(v.x), "=f"(v.y), "=f"(v.z), "=f"(v.w) : "l"(p));
    return v;
}

// ---------------- reductions ----------------
__device__ __forceinline__ float wred(float v) {
#pragma unroll
    for (int o = 16; o > 0; o >>= 1) v += __shfl_xor_sync(0xffffffffu, v, o);
    return v;
}
__device__ __forceinline__ float bred512(float v, float* sbuf) {
    int tid = threadIdx.x;
#pragma unroll
    for (int o = 16; o > 0; o >>= 1) v += __shfl_down_sync(0xffffffffu, v, o);
    if ((tid & 31) == 0) sbuf[tid >> 5] = v;
    __syncthreads();
    if (tid < 32) {
        float r = (tid < 16) ? sbuf[tid] : 0.f;
#pragma unroll
        for (int o = 8; o > 0; o >>= 1) r += __shfl_down_sync(0xffffffffu, r, o);
        if (tid == 0) sbuf[0] = r;
    }
    __syncthreads();
    float r = sbuf[0];
    __syncthreads();
    return r;
}

// ---------------- global barrier (CUDA-samples pattern) ----------------
__device__ __forceinline__ void gbar(int idx) {
    __threadfence();
    __syncthreads();
    if (threadIdx.x == 0) {
        atomicAdd(&g_bar[idx], 1u);
        unsigned v;
        while (true) {
            asm volatile("ld.acquire.gpu.global.u32 %0, [%1];"
                         : "=r"(v) : "l"(&g_bar[idx]) : "memory");
            if (v >= (unsigned)NBLK) break;
            __nanosleep(128);
        }
    }
    __syncthreads();
}

// ---------------- pipeline state ----------------
struct PipeState { int consumed; int issued; int total; };

__device__ __forceinline__ void issue_one(PipeState& p, char* sm) {
    if (p.issued < p.total) {
        int slot = p.issued % NBUF;
        uint32_t mb = s2u(sm) + 8u * slot;
        const float* src = ((const float* const*)(sm + TAB_OFF))[p.issued];
        MB_EXPECT(mb, STAGE_BYTES);
        bulk_g2s(s2u(sm) + ST_OFF + slot * STAGE_BYTES, src, STAGE_BYTES, mb);
        p.issued++;
    }
}

#define CONSUME_BEGIN(nst)                                                     \
    for (int _i = 0; _i < (nst); _i++) {                                       \
        int _slot = P.consumed % NBUF, _par = (P.consumed / NBUF) & 1;         \
        MB_WAIT(s2u(sm) + 8u * _slot, _par);                                   \
        const float* buf = (const float*)(sm + ST_OFF + _slot * STAGE_BYTES);

#define CONSUME_END                                                            \
        __syncthreads();                                                       \
        if (tid == 0) issue_one(P, sm);                                        \
        P.consumed++;                                                          \
    }

// ---------------- the mega kernel ----------------
__global__ void __launch_bounds__(NTHR) k_mega(
    const float* __restrict__ past, const float* __restrict__ emb,
    const int* __restrict__ tok,
    const float* __restrict__ Wq, const float* __restrict__ Wk,
    const float* __restrict__ Wv, const float* __restrict__ Wo,
    const float* __restrict__ qn, const float* __restrict__ kn,
    const float* __restrict__ ln1, const float* __restrict__ ln2,
    const float* __restrict__ Wg, const float* __restrict__ Wu,
    const float* __restrict__ Wd, const float* __restrict__ fn,
    const float* __restrict__ lm,
    float* __restrict__ logits, float* __restrict__ kvc) {
    extern __shared__ char sm[];
    const int b = blockIdx.x;
    const int tid = threadIdx.x;
    float* sbuf = (float*)(sm + SBUF_OFF);
    float2* xs2 = (float2*)(sm + XS_OFF);
    float* xsf = (float*)(sm + XS_OFF);
    float* sc = (float*)(sm + 48);

    // -- mbarrier init --
    if (tid == 0) {
#pragma unroll
        for (int s = 0; s < NBUF; s++) MB_INIT(s2u(sm) + 8u * s, 1);
    }
    __syncthreads();

    // -- build lifetime stage table + prime pipeline (tid 0) --
    PipeState P; P.consumed = 0; P.issued = 0; P.total = 0;
    int c0 = (b * 960) / NBLK, c1 = ((b + 1) * 960) / NBLK;  // lm chunks
    if (tid == 0) {
        const float** tab = (const float**)(sm + TAB_OFF);
        int n = 0;
        for (int l = 0; l < NLAYER; l++) {
            if (b < 96) {
                const float* W = (b >> 5) == 0 ? Wq : ((b >> 5) == 1 ? Wk : Wv);
                const float* base = W + (size_t)l * DIM * DIM +
                                    (size_t)(b & 31) * 32 * DIM;
                for (int s = 0; s < 4; s++) tab[n++] = base + (size_t)s * STAGE_FLOATS;
            }
            if (b < 64) {
                const float* base = Wo + (size_t)l * DIM * DIM + (size_t)b * 16 * DIM;
                tab[n++] = base;
                tab[n++] = base + STAGE_FLOATS;
            }
            if (b < 128) {
                const float* W = (b >> 6) ? Wu : Wg;
                const float* base = W + (size_t)l * DIM * FF +
                                    (size_t)(b & 63) * 16 * FF;
                for (int s = 0; s < 8; s++) tab[n++] = base + (size_t)s * STAGE_FLOATS;
            }
            if (b < 128) {
                const float* base = Wd + (size_t)l * FF * DIM + (size_t)b * 32 * DIM;
                for (int s = 0; s < 4; s++) tab[n++] = base + (size_t)s * STAGE_FLOATS;
            }
        }
        for (int c = c0; c < c1; c++) {
            const float* base = lm + (size_t)(c >> 6) * DIM * VOC +
                                (size_t)(c & 63) * 16 * VOC;
            for (int s = 0; s < 4; s++) tab[n++] = base + (size_t)s * STAGE_FLOATS;
        }
        P.total = n;
#pragma unroll
        for (int s = 0; s < NBUF; s++) issue_one(P, sm);
    }

    // -- init phase: embed + zero logits/qkv --
    {
        int gi = b * NTHR + tid;
        if (gi < NLM * VOC) logits[gi] = 0.f;
        else if (gi < NLM * VOC + 6 * DIM) g_qkv[gi - NLM * VOC] = 0.f;
        else if (gi < NLM * VOC + 6 * DIM + DIM) {
            int i = gi - (NLM * VOC + 6 * DIM);
            g_h[i] = past[i];
        } else if (gi < NLM * VOC + 6 * DIM + 2 * DIM) {
            int i = gi - (NLM * VOC + 7 * DIM);
            g_h[DIM + i] = emb[(size_t)tok[0] * DIM + i];
        }
    }
    gbar(0);

    for (int l = 0; l < NLAYER; l++) {
        // ===== phase QKV =====
        if (b < 96) {
            int mat = b >> 5, rch = b & 31;
            float s0 = 0.f, s1 = 0.f;
#pragma unroll
            for (int i = 0; i < 2; i++) {
                int idx = tid + i * NTHR;
                float a = ldcg(&g_h[idx]), c = ldcg(&g_h[DIM + idx]);
                s0 += a * a; s1 += c * c;
            }
            s0 = bred512(s0, sbuf);
            s1 = bred512(s1, sbuf);
            float r0 = rsqrtf(s0 * (1.f / DIM) + EPSF);
            float r1 = rsqrtf(s1 * (1.f / DIM) + EPSF);
            if (tid < 32) {
                int idx = rch * 32 + tid;
                float wl = ln1[l * DIM + idx];
                xs2[tid] = make_float2(ldcg(&g_h[idx]) * r0 * wl,
                                       ldcg(&g_h[DIM + idx]) * r1 * wl);
            }
            __syncthreads();
            float a00 = 0.f, a01 = 0.f, a10 = 0.f, a11 = 0.f;
            CONSUME_BEGIN(4)
                const float2* bw = (const float2*)buf;
#pragma unroll
                for (int r = 0; r < 8; r++) {
                    float2 w = bw[r * NTHR + tid];
                    float2 x = xs2[_i * 8 + r];
                    a00 = fmaf(w.x, x.x, a00); a01 = fmaf(w.y, x.x, a01);
                    a10 = fmaf(w.x, x.y, a10); a11 = fmaf(w.y, x.y, a11);
                }
            CONSUME_END
            float* o = g_qkv + mat * 2048;
            red2(o + 2 * tid, a00, a01);
            red2(o + DIM + 2 * tid, a10, a11);
        } else if (b < 128) {
            g_gu[(b - 96) * NTHR + tid] = 0.f;   // zero for this layer's gateup
        }
        gbar(1 + 4 * l);

        // ===== phase WO + attention =====
        if (b < 64) {
            int hh = b >> 3;
            if (tid < 32) {
                int lane = tid;
                float4 q1 = ldcg4(g_qkv + DIM + hh * HD + 4 * lane);
                float4 k0 = ldcg4(g_qkv + 2048 + hh * HD + 4 * lane);
                float4 k1 = ldcg4(g_qkv + 2048 + DIM + hh * HD + 4 * lane);
                float nq1 = wred(q1.x * q1.x + q1.y * q1.y + q1.z * q1.z + q1.w * q1.w);
                float nk0 = wred(k0.x * k0.x + k0.y * k0.y + k0.z * k0.z + k0.w * k0.w);
                float nk1 = wred(k1.x * k1.x + k1.y * k1.y + k1.z * k1.z + k1.w * k1.w);
                float rq1 = rsqrtf(nq1 * (1.f / HD) + EPSF);
                float rk0 = rsqrtf(nk0 * (1.f / HD) + EPSF);
                float rk1 = rsqrtf(nk1 * (1.f / HD) + EPSF);
                float4 qn4 = ((const float4*)(qn + l * HD))[lane];
                float4 kn4 = ((const float4*)(kn + l * HD))[lane];
                q1.x *= rq1 * qn4.x; q1.y *= rq1 * qn4.y;
                q1.z *= rq1 * qn4.z; q1.w *= rq1 * qn4.w;
                k0.x *= rk0 * kn4.x; k0.y *= rk0 * kn4.y;
                k0.z *= rk0 * kn4.z; k0.w *= rk0 * kn4.w;
                k1.x *= rk1 * kn4.x; k1.y *= rk1 * kn4.y;
                k1.z *= rk1 * kn4.z; k1.w *= rk1 * kn4.w;
                int jb = 4 * (lane & 15);
                const float C = 9.210340371976184f / 64.f;  // ln(1e4)/64
                float an0 = expf(-(float)(jb + 0) * C);
                float an1 = expf(-(float)(jb + 1) * C);
                float an2 = expf(-(float)(jb + 2) * C);
                float an3 = expf(-(float)(jb + 3) * C);
                float csx = cosf(an0), snx = sinf(an0);
                float csy = cosf(an1), sny = sinf(an1);
                float csz = cosf(an2), snz = sinf(an2);
                float csw = cosf(an3), snw = sinf(an3);
                float sgn = (lane < 16) ? -1.f : 1.f;
                float4 pq, pk;
                pq.x = __shfl_xor_sync(0xffffffffu, q1.x, 16);
                pq.y = __shfl_xor_sync(0xffffffffu, q1.y, 16);
                pq.z = __shfl_xor_sync(0xffffffffu, q1.z, 16);
                pq.w = __shfl_xor_sync(0xffffffffu, q1.w, 16);
                pk.x = __shfl_xor_sync(0xffffffffu, k1.x, 16);
                pk.y = __shfl_xor_sync(0xffffffffu, k1.y, 16);
                pk.z = __shfl_xor_sync(0xffffffffu, k1.z, 16);
                pk.w = __shfl_xor_sync(0xffffffffu, k1.w, 16);
                q1.x = q1.x * csx + sgn * pq.x * snx;
                q1.y = q1.y * csy + sgn * pq.y * sny;
                q1.z = q1.z * csz + sgn * pq.z * snz;
                q1.w = q1.w * csw + sgn * pq.w * snw;
                k1.x = k1.x * csx + sgn * pk.x * snx;
                k1.y = k1.y * csy + sgn * pk.y * sny;
                k1.z = k1.z * csz + sgn * pk.z * snz;
                k1.w = k1.w * csw + sgn * pk.w * snw;
                float d10 = wred(q1.x * k0.x + q1.y * k0.y + q1.z * k0.z + q1.w * k0.w);
                float d11 = wred(q1.x * k1.x + q1.y * k1.y + q1.z * k1.z + q1.w * k1.w);
                const float scale = 0.08838834764831845f;
                float s10 = d10 * scale, s11 = d11 * scale;
                float m = fmaxf(s10, s11);
                float e0 = expf(s10 - m), e1 = expf(s11 - m);
                float inv = 1.f / (e0 + e1);
                if (lane == 0) { sc[0] = e0; sc[1] = e1; sc[2] = inv; }
                if ((b & 7) == 0) {
                    float4 v0 = ldcg4(g_qkv + 4096 + hh * HD + 4 * lane);
                    float4 v1 = ldcg4(g_qkv + 4096 + DIM + hh * HD + 4 * lane);
                    float* kv = kvc + (size_t)l * 4096;
                    ((float4*)(kv + hh * 256))[lane] = k0;
                    ((float4*)(kv + hh * 256 + HD))[lane] = k1;
                    ((float4*)(kv + 2048 + hh * 256))[lane] = v0;
                    ((float4*)(kv + 2048 + hh * 256 + HD))[lane] = v1;
                }
            }
            __syncthreads();
            if (tid < 16) {
                int dim = b * 16 + tid;
                float v0 = ldcg(&g_qkv[4096 + dim]);
                float v1 = ldcg(&g_qkv[4096 + DIM + dim]);
                xs2[tid] = make_float2(v0, (sc[0] * v0 + sc[1] * v1) * sc[2]);
            }
            __syncthreads();
            float a00 = 0.f, a01 = 0.f, a10 = 0.f, a11 = 0.f;
            CONSUME_BEGIN(2)
                const float2* bw = (const float2*)buf;
#pragma unroll
                for (int r = 0; r < 8; r++) {
                    float2 w = bw[r * NTHR + tid];
                    float2 x = xs2[_i * 8 + r];
                    a00 = fmaf(w.x, x.x, a00); a01 = fmaf(w.y, x.x, a01);
                    a10 = fmaf(w.x, x.y, a10); a11 = fmaf(w.y, x.y, a11);
                }
            CONSUME_END
            red2(g_h + 2 * tid, a00, a01);
            red2(g_h + DIM + 2 * tid, a10, a11);
        }
        gbar(2 + 4 * l);

        // ===== phase GATEUP =====
        if (b < 128) {
            int mat = b >> 6, rch = b & 63;
            float s0 = 0.f, s1 = 0.f;
#pragma unroll
            for (int i = 0; i < 2; i++) {
                int idx = tid + i * NTHR;
                float a = ldcg(&g_h[idx]), c = ldcg(&g_h[DIM + idx]);
                s0 += a * a; s1 += c * c;
            }
            s0 = bred512(s0, sbuf);
            s1 = bred512(s1, sbuf);
            float r0 = rsqrtf(s0 * (1.f / DIM) + EPSF);
            float r1 = rsqrtf(s1 * (1.f / DIM) + EPSF);
            if (tid < 16) {
                int idx = rch * 16 + tid;
                float wl = ln2[l * DIM + idx];
                xs2[tid] = make_float2(ldcg(&g_h[idx]) * r0 * wl,
                                       ldcg(&g_h[DIM + idx]) * r1 * wl);
            }
            __syncthreads();
            float4 A00 = {0,0,0,0}, A01 = {0,0,0,0}, A10 = {0,0,0,0}, A11 = {0,0,0,0};
            CONSUME_BEGIN(8)
                const float4* b4 = (const float4*)buf;
#pragma unroll
                for (int r = 0; r < 2; r++) {
                    float2 x = xs2[_i * 2 + r];
                    float4 w0 = b4[r * 1024 + tid];
                    float4 w1 = b4[r * 1024 + NTHR + tid];
                    A00.x = fmaf(w0.x, x.x, A00.x); A00.y = fmaf(w0.y, x.x, A00.y);
                    A00.z = fmaf(w0.z, x.x, A00.z); A00.w = fmaf(w0.w, x.x, A00.w);
                    A10.x = fmaf(w0.x, x.y, A10.x); A10.y = fmaf(w0.y, x.y, A10.y);
                    A10.z = fmaf(w0.z, x.y, A10.z); A10.w = fmaf(w0.w, x.y, A10.w);
                    A01.x = fmaf(w1.x, x.x, A01.x); A01.y = fmaf(w1.y, x.x, A01.y);
                    A01.z = fmaf(w1.z, x.x, A01.z); A01.w = fmaf(w1.w, x.x, A01.w);
                    A11.x = fmaf(w1.x, x.y, A11.x); A11.y = fmaf(w1.y, x.y, A11.y);
                    A11.z = fmaf(w1.z, x.y, A11.z); A11.w = fmaf(w1.w, x.y, A11.w);
                }
            CONSUME_END
            float* o = g_gu + mat * 8192;
            red4(o + 4 * tid, A00);
            red4(o + 2048 + 4 * tid, A01);
            red4(o + FF + 4 * tid, A10);
            red4(o + FF + 2048 + 4 * tid, A11);
        }
        gbar(3 + 4 * l);

        // ===== phase DOWN =====
        if (b < 128) {
            if (tid < 32) {
                int idx = b * 32 + tid;
                float g0 = ldcg(&g_gu[idx]),        g1 = ldcg(&g_gu[FF + idx]);
                float u0 = ldcg(&g_gu[8192 + idx]), u1 = ldcg(&g_gu[8192 + FF + idx]);
                xs2[tid] = make_float2(g0 / (1.f + expf(-g0)) * u0,
                                       g1 / (1.f + expf(-g1)) * u1);
            }
            __syncthreads();
            float a00 = 0.f, a01 = 0.f, a10 = 0.f, a11 = 0.f;
            CONSUME_BEGIN(4)
                const float2* bw = (const float2*)buf;
#pragma unroll
                for (int r = 0; r < 8; r++) {
                    float2 w = bw[r * NTHR + tid];
                    float2 x = xs2[_i * 8 + r];
                    a00 = fmaf(w.x, x.x, a00); a01 = fmaf(w.y, x.x, a01);
                    a10 = fmaf(w.x, x.y, a10); a11 = fmaf(w.y, x.y, a11);
                }
            CONSUME_END
            red2(g_h + 2 * tid, a00, a01);
            red2(g_h + DIM + 2 * tid, a10, a11);
        }
        if (b < 12) g_qkv[b * NTHR + tid] = 0.f;   // zero for next layer's qkv
        gbar(4 + 4 * l);
    }

    // ===== phase LM =====
    {
        float s = 0.f;
#pragma unroll
        for (int i = 0; i < 2; i++) {
            float v = ldcg(&g_h[DIM + tid + i * NTHR]);
            s += v * v;
        }
        s = bred512(s, sbuf);
        float r = rsqrtf(s * (1.f / DIM) + EPSF);
#pragma unroll
        for (int i = 0; i < 2; i++) {
            int idx = tid + i * NTHR;
            xsf[idx] = ldcg(&g_h[DIM + idx]) * r * fn[idx];
        }
        __syncthreads();

        float4 A = {0, 0, 0, 0};
        int curmat = -1;
        for (int c = c0; c < c1; c++) {
            int mat = c >> 6;
            if (mat != curmat) {
                if (curmat >= 0)
                    red4(logits + (size_t)curmat * VOC + 4 * tid, A);
                A = make_float4(0.f, 0.f, 0.f, 0.f);
                curmat = mat;
            }
            int rbase0 = (c & 63) * 16;
            CONSUME_BEGIN(4)
                const float4* b4 = (const float4*)buf;
#pragma unroll
                for (int r = 0; r < 4; r++) {
                    float x = xsf[rbase0 + _i * 4 + r];
                    float4 w = b4[r * NTHR + tid];
                    A.x = fmaf(w.x, x, A.x); A.y = fmaf(w.y, x, A.y);
                    A.z = fmaf(w.z, x, A.z); A.w = fmaf(w.w, x, A.w);
                }
            CONSUME_END
        }
        if (curmat >= 0) red4(logits + (size_t)curmat * VOC + 4 * tid, A);
    }

    // ===== finish: restore barrier state for next launch =====
    __syncthreads();
    if (tid == 0) {
        unsigned old = atomicAdd(&g_fin, 1u);
        if (old == (unsigned)(NBLK - 1)) {
            for (int i = 0; i < 21; i++) g_bar[i] = 0u;
            __threadfence();
            g_fin = 0u;
        }
    }
}

// ---------------- host launcher ----------------
extern "C" void kernel_launch(void* const* d_in, const int* in_sizes, int n_in,
                              void* d_out, int out_size) {
    const float *past, *emb, *Wq, *Wk, *Wv, *Wo, *qn, *kn, *ln1, *ln2, *Wg, *Wu,
        *Wd, *fn, *lm;
    const int* tok;
    if (in_sizes[1] == 1) {
        past = (const float*)d_in[0];
        tok  = (const int*)d_in[1];
        emb  = (const float*)d_in[2];
        Wq = (const float*)d_in[3];  Wk = (const float*)d_in[4];
        Wv = (const float*)d_in[5];  Wo = (const float*)d_in[6];
        qn = (const float*)d_in[7];  kn = (const float*)d_in[8];
        ln1 = (const float*)d_in[9]; ln2 = (const float*)d_in[10];
        Wg = (const float*)d_in[11]; Wu = (const float*)d_in[12];
        Wd = (const float*)d_in[13]; fn = (const float*)d_in[14];
        lm = (const float*)d_in[15];
    } else {
        past = (const float*)d_in[0];
        emb  = (const float*)d_in[1];
        Wq = (const float*)d_in[2];  Wk = (const float*)d_in[3];
        Wv = (const float*)d_in[4];  Wo = (const float*)d_in[5];
        qn = (const float*)d_in[6];  kn = (const float*)d_in[7];
        ln1 = (const float*)d_in[8]; ln2 = (const float*)d_in[9];
        Wg = (const float*)d_in[10]; Wu = (const float*)d_in[11];
        Wd = (const float*)d_in[12]; fn = (const float*)d_in[13];
        lm = (const float*)d_in[14];
        tok = (const int*)d_in[15];
    }

    static bool attr_done = false;
    if (!attr_done) {
        cudaFuncSetAttribute(k_mega, cudaFuncAttributeMaxDynamicSharedMemorySize,
                             SM_TOTAL);
        attr_done = true;
    }

    float* out = (float*)d_out;
    float* logits = out;             // [15][2048]
    float* kvc = out + NLM * VOC;    // [10][8][2][128]

    k_mega<<<NBLK, NTHR, SM_TOTAL>>>(past, emb, tok, Wq, Wk, Wv, Wo, qn, kn,
                                     ln1, ln2, Wg, Wu, Wd, fn, lm, logits, kvc);
    (void)n_in; (void)out_size;
}

// round 6
// speedup vs baseline: 1.2469x; 1.0370x over previous
#include <cuda_runtime.h>
#include <cuda_bf16.h>
#include <math.h>
#include <stdint.h>

#define DIM    1024
#define HD     128
#define FF     4096
#define VOC    2048
#define NLM    15
#define NLAYER 5
#define EPSF   1e-6f
#define NBLK   148
#define CTHR   512          // compute threads
#define NTHR   544          // + producer warp

#define NBUF         12
#define STAGE_BYTES  16384
#define STAGE_FLOATS 4096
// smem: [0,96) full mbarriers | [96,192) empty mbarriers | [192,208) sc
// [256,4352) xs | [4352,4416) sbuf | [4480,6400) stage table (240 ptrs)
// [8192, +12*16K) stages
#define MBF_OFF  0
#define MBE_OFF  96
#define SC_OFF   192
#define XS_OFF   256
#define SBUF_OFF 4352
#define TAB_OFF  4480
#define ST_OFF   8192
#define SM_TOTAL (ST_OFF + NBUF * STAGE_BYTES)   // 204800

// ---------------- device scratch ----------------
__device__ float g_h[2 * DIM];
__device__ float g_qkv[6 * DIM];   // q[2][1024] | k[2][1024] | v[2][1024]
__device__ float g_gu[4 * FF];     // gate[2][4096] | up[2][4096]
__device__ unsigned g_bar[32];     // zero-init; restored at end of run
__device__ unsigned g_fin;

// ---------------- PTX helpers ----------------
__device__ __forceinline__ uint32_t s2u(const void* p) {
    uint32_t a;
    asm("{ .reg .u64 t; cvta.to.shared.u64 t, %1; cvt.u32.u64 %0, t; }"
        : "=r"(a) : "l"(p));
    return a;
}
#define MB_INIT(mbar, cnt) \
    asm volatile("mbarrier.init.shared.b64 [%0], %1;" :: "r"(mbar), "r"(cnt) : "memory")
#define MB_EXPECT(mbar, bytes) \
    asm volatile("mbarrier.arrive.expect_tx.shared.b64 _, [%0], %1;" :: "r"(mbar), "r"(bytes) : "memory")
#define MB_ARRIVE(mbar) \
    asm volatile("mbarrier.arrive.shared.b64 _, [%0];" :: "r"(mbar) : "memory")
#define MB_WAIT(mbar, ph) do {                                                   \
    asm volatile("{\n\t.reg .pred P1;\n\t"                                       \
        "W_%=:\n\t"                                                              \
        "mbarrier.try_wait.parity.acquire.cta.shared::cta.b64 P1, [%0], %1, 0x989680;\n\t" \
        "@P1 bra.uni D_%=;\n\t"                                                  \
        "bra.uni W_%=;\n\t"                                                      \
        "D_%=:\n\t}"                                                             \
        :: "r"(mbar), "r"(ph) : "memory");                                       \
} while (0)
#define CBAR() asm volatile("bar.sync 1, %0;" :: "n"(CTHR) : "memory")
__device__ __forceinline__ void bulk_g2s(uint32_t dst, const void* src,
                                         uint32_t bytes, uint32_t mbar) {
    asm volatile(
        "cp.async.bulk.shared::cluster.global.mbarrier::complete_tx::bytes "
        "[%0], [%1], %2, [%3];"
        :: "r"(dst), "l"(src), "r"(bytes), "r"(mbar) : "memory");
}
__device__ __forceinline__ void red2(float* p, float a, float b) {
    asm volatile("red.global.add.v2.f32 [%0], {%1, %2};"
                 :: "l"(p), "f"(a), "f"(b) : "memory");
}
__device__ __forceinline__ void red4(float* p, float4 v) {
    asm volatile("red.global.add.v4.f32 [%0], {%1, %2, %3, %4};"
                 :: "l"(p), "f"(v.x), "f"(v.y), "f"(v.z), "f"(v.w) : "memory");
}
__device__ __forceinline__ float ldcg(const float* p) {
    float v;
    asm volatile("ld.global.cg.f32 %0, [%1];" : "=f"(v) : "l"(p));
    return v;
}
__device__ __forceinline__ float4 ldcg4(const float* p) {
    float4 v;
    asm volatile("ld.global.cg.v4.f32 {%0,%1,%2,%3}, [%4];"
                 : "=f"(v.x), "=f"(v.y), "=f"(v.z), "=f"(v.w) : "l"(p));
    return v;
}

// ---------------- reductions ----------------
__device__ __forceinline__ float wred(float v) {
#pragma unroll
    for (int o = 16; o > 0; o >>= 1) v += __shfl_xor_sync(0xffffffffu, v, o);
    return v;
}
// 512-compute-thread reduce (uses named barrier 1)
__device__ __forceinline__ float bred512(float v, float* sbuf) {
    int tid = threadIdx.x;
#pragma unroll
    for (int o = 16; o > 0; o >>= 1) v += __shfl_down_sync(0xffffffffu, v, o);
    if ((tid & 31) == 0) sbuf[tid >> 5] = v;
    CBAR();
    if (tid < 32) {
        float r = (tid < 16) ? sbuf[tid] : 0.f;
#pragma unroll
        for (int o = 8; o > 0; o >>= 1) r += __shfl_down_sync(0xffffffffu, r, o);
        if (tid == 0) sbuf[0] = r;
    }
    CBAR();
    float r = sbuf[0];
    CBAR();
    return r;
}

// ---------------- global barrier over compute threads ----------------
__device__ __forceinline__ void gbar(int idx) {
    __threadfence();
    CBAR();
    if (threadIdx.x == 0) {
        atomicAdd(&g_bar[idx], 1u);
        unsigned v;
        while (true) {
            asm volatile("ld.acquire.gpu.global.u32 %0, [%1];"
                         : "=r"(v) : "l"(&g_bar[idx]) : "memory");
            if (v >= (unsigned)NBLK) break;
            __nanosleep(128);
        }
    }
    CBAR();
}

// consumer-side ring macros (512 compute threads; cursor = consumed)
#define CONSUME_BEGIN(nst)                                                     \
    for (int _i = 0; _i < (nst); _i++) {                                       \
        int _slot = consumed % NBUF, _par = (consumed / NBUF) & 1;             \
        MB_WAIT(mbf + 8u * _slot, _par);                                       \
        const float* buf = (const float*)(sm + ST_OFF + _slot * STAGE_BYTES);

#define CONSUME_END                                                            \
        CBAR();                                                                \
        if (tid == 0) MB_ARRIVE(mbe + 8u * _slot);                             \
        consumed++;                                                            \
    }

// ---------------- mega kernel ----------------
__global__ void __launch_bounds__(NTHR) k_mega(
    const float* __restrict__ past, const float* __restrict__ emb,
    const int* __restrict__ tok,
    const float* __restrict__ Wq, const float* __restrict__ Wk,
    const float* __restrict__ Wv, const float* __restrict__ Wo,
    const float* __restrict__ qn, const float* __restrict__ kn,
    const float* __restrict__ ln1, const float* __restrict__ ln2,
    const float* __restrict__ Wg, const float* __restrict__ Wu,
    const float* __restrict__ Wd, const float* __restrict__ fn,
    const float* __restrict__ lm,
    float* __restrict__ logits, float* __restrict__ kvc) {
    extern __shared__ char sm[];
    const int b = blockIdx.x;
    const int tid = threadIdx.x;
    const uint32_t mbf = s2u(sm) + MBF_OFF;
    const uint32_t mbe = s2u(sm) + MBE_OFF;
    float* sbuf = (float*)(sm + SBUF_OFF);
    float2* xs2 = (float2*)(sm + XS_OFF);
    float* xsf = (float*)(sm + XS_OFF);
    float* sc = (float*)(sm + SC_OFF);
    int c0 = (b * 960) / NBLK, c1 = ((b + 1) * 960) / NBLK;  // lm chunks

    if (tid == CTHR) {   // producer inits all mbarriers
#pragma unroll
        for (int s = 0; s < NBUF; s++) {
            MB_INIT(mbf + 8u * s, 1);
            MB_INIT(mbe + 8u * s, 1);
        }
    }
    __syncthreads();     // only block-wide sync; before role split

    // ================= producer warp =================
    if (tid >= CTHR) {
        if (tid == CTHR) {
            const float** tab = (const float**)(sm + TAB_OFF);
            int n = 0;
            for (int l = 0; l < NLAYER; l++) {
                if (b < 96) {
                    const float* W = (b >> 5) == 0 ? Wq : ((b >> 5) == 1 ? Wk : Wv);
                    const float* base = W + (size_t)l * DIM * DIM +
                                        (size_t)(b & 31) * 32 * DIM;
                    for (int s = 0; s < 8; s++)
                        tab[n++] = base + (size_t)s * STAGE_FLOATS;
                }
                if (b < 64) {
                    const float* base = Wo + (size_t)l * DIM * DIM +
                                        (size_t)b * 16 * DIM;
                    for (int s = 0; s < 4; s++)
                        tab[n++] = base + (size_t)s * STAGE_FLOATS;
                }
                if (b < 128) {
                    const float* W = (b >> 6) ? Wu : Wg;
                    const float* base = W + (size_t)l * DIM * FF +
                                        (size_t)(b & 63) * 16 * FF;
                    for (int s = 0; s < 16; s++)
                        tab[n++] = base + (size_t)s * STAGE_FLOATS;
                }
                if (b < 128) {
                    const float* base = Wd + (size_t)l * FF * DIM +
                                        (size_t)b * 32 * DIM;
                    for (int s = 0; s < 8; s++)
                        tab[n++] = base + (size_t)s * STAGE_FLOATS;
                }
            }
            for (int c = c0; c < c1; c++) {
                const float* base = lm + (size_t)(c >> 6) * DIM * VOC +
                                    (size_t)(c & 63) * 16 * VOC;
                for (int s = 0; s < 8; s++)
                    tab[n++] = base + (size_t)s * STAGE_FLOATS;
            }
            // stream everything; throttled only by empty-slot arrivals
            for (int i = 0; i < n; i++) {
                int slot = i % NBUF;
                if (i >= NBUF) {
                    int par = ((i / NBUF) - 1) & 1;
                    MB_WAIT(mbe + 8u * slot, par);
                }
                MB_EXPECT(mbf + 8u * slot, STAGE_BYTES);
                bulk_g2s(s2u(sm) + ST_OFF + slot * STAGE_BYTES, tab[i],
                         STAGE_BYTES, mbf + 8u * slot);
            }
        }
        return;   // producer warp exits; named barriers use 512 threads only
    }

    // ================= compute threads (512) =================
    int consumed = 0;

    // init: zero logits/qkv, embed
    {
        int gi = b * CTHR + tid;
        if (gi < NLM * VOC) logits[gi] = 0.f;
        else if (gi < NLM * VOC + 6 * DIM) g_qkv[gi - NLM * VOC] = 0.f;
        else if (gi < NLM * VOC + 6 * DIM + DIM) {
            int i = gi - (NLM * VOC + 6 * DIM);
            g_h[i] = past[i];
        } else if (gi < NLM * VOC + 6 * DIM + 2 * DIM) {
            int i = gi - (NLM * VOC + 7 * DIM);
            g_h[DIM + i] = emb[(size_t)tok[0] * DIM + i];
        }
    }
    gbar(0);

    for (int l = 0; l < NLAYER; l++) {
        // ===== QKV =====
        if (b < 96) {
            int mat = b >> 5, rch = b & 31;
            float s0 = 0.f, s1 = 0.f;
#pragma unroll
            for (int i = 0; i < 2; i++) {
                int idx = tid + i * CTHR;
                float a = ldcg(&g_h[idx]), c = ldcg(&g_h[DIM + idx]);
                s0 += a * a; s1 += c * c;
            }
            s0 = bred512(s0, sbuf);
            s1 = bred512(s1, sbuf);
            float r0 = rsqrtf(s0 * (1.f / DIM) + EPSF);
            float r1 = rsqrtf(s1 * (1.f / DIM) + EPSF);
            if (tid < 32) {
                int idx = rch * 32 + tid;
                float wl = ln1[l * DIM + idx];
                xs2[tid] = make_float2(ldcg(&g_h[idx]) * r0 * wl,
                                       ldcg(&g_h[DIM + idx]) * r1 * wl);
            }
            CBAR();
            float a00 = 0.f, a01 = 0.f, a10 = 0.f, a11 = 0.f;
            CONSUME_BEGIN(8)
                const float2* bw = (const float2*)buf;
#pragma unroll
                for (int r = 0; r < 4; r++) {
                    float2 w = bw[r * CTHR + tid];
                    float2 x = xs2[_i * 4 + r];
                    a00 = fmaf(w.x, x.x, a00); a01 = fmaf(w.y, x.x, a01);
                    a10 = fmaf(w.x, x.y, a10); a11 = fmaf(w.y, x.y, a11);
                }
            CONSUME_END
            float* o = g_qkv + mat * 2048;
            red2(o + 2 * tid, a00, a01);
            red2(o + DIM + 2 * tid, a10, a11);
        } else if (b < 128) {
            g_gu[(b - 96) * CTHR + tid] = 0.f;   // zero this layer's g_gu
        }
        gbar(1 + 4 * l);

        // ===== WO + attention =====
        if (b < 64) {
            int hh = b >> 3;
            if (tid < 32) {
                int lane = tid;
                float4 q1 = ldcg4(g_qkv + DIM + hh * HD + 4 * lane);
                float4 k0 = ldcg4(g_qkv + 2048 + hh * HD + 4 * lane);
                float4 k1 = ldcg4(g_qkv + 2048 + DIM + hh * HD + 4 * lane);
                float nq1 = wred(q1.x * q1.x + q1.y * q1.y + q1.z * q1.z + q1.w * q1.w);
                float nk0 = wred(k0.x * k0.x + k0.y * k0.y + k0.z * k0.z + k0.w * k0.w);
                float nk1 = wred(k1.x * k1.x + k1.y * k1.y + k1.z * k1.z + k1.w * k1.w);
                float rq1 = rsqrtf(nq1 * (1.f / HD) + EPSF);
                float rk0 = rsqrtf(nk0 * (1.f / HD) + EPSF);
                float rk1 = rsqrtf(nk1 * (1.f / HD) + EPSF);
                float4 qn4 = ((const float4*)(qn + l * HD))[lane];
                float4 kn4 = ((const float4*)(kn + l * HD))[lane];
                q1.x *= rq1 * qn4.x; q1.y *= rq1 * qn4.y;
                q1.z *= rq1 * qn4.z; q1.w *= rq1 * qn4.w;
                k0.x *= rk0 * kn4.x; k0.y *= rk0 * kn4.y;
                k0.z *= rk0 * kn4.z; k0.w *= rk0 * kn4.w;
                k1.x *= rk1 * kn4.x; k1.y *= rk1 * kn4.y;
                k1.z *= rk1 * kn4.z; k1.w *= rk1 * kn4.w;
                int jb = 4 * (lane & 15);
                const float C = 9.210340371976184f / 64.f;
                float an0 = expf(-(float)(jb + 0) * C);
                float an1 = expf(-(float)(jb + 1) * C);
                float an2 = expf(-(float)(jb + 2) * C);
                float an3 = expf(-(float)(jb + 3) * C);
                float csx = cosf(an0), snx = sinf(an0);
                float csy = cosf(an1), sny = sinf(an1);
                float csz = cosf(an2), snz = sinf(an2);
                float csw = cosf(an3), snw = sinf(an3);
                float sgn = (lane < 16) ? -1.f : 1.f;
                float4 pq, pk;
                pq.x = __shfl_xor_sync(0xffffffffu, q1.x, 16);
                pq.y = __shfl_xor_sync(0xffffffffu, q1.y, 16);
                pq.z = __shfl_xor_sync(0xffffffffu, q1.z, 16);
                pq.w = __shfl_xor_sync(0xffffffffu, q1.w, 16);
                pk.x = __shfl_xor_sync(0xffffffffu, k1.x, 16);
                pk.y = __shfl_xor_sync(0xffffffffu, k1.y, 16);
                pk.z = __shfl_xor_sync(0xffffffffu, k1.z, 16);
                pk.w = __shfl_xor_sync(0xffffffffu, k1.w, 16);
                q1.x = q1.x * csx + sgn * pq.x * snx;
                q1.y = q1.y * csy + sgn * pq.y * sny;
                q1.z = q1.z * csz + sgn * pq.z * snz;
                q1.w = q1.w * csw + sgn * pq.w * snw;
                k1.x = k1.x * csx + sgn * pk.x * snx;
                k1.y = k1.y * csy + sgn * pk.y * sny;
                k1.z = k1.z * csz + sgn * pk.z * snz;
                k1.w = k1.w * csw + sgn * pk.w * snw;
                float d10 = wred(q1.x * k0.x + q1.y * k0.y + q1.z * k0.z + q1.w * k0.w);
                float d11 = wred(q1.x * k1.x + q1.y * k1.y + q1.z * k1.z + q1.w * k1.w);
                const float scale = 0.08838834764831845f;
                float s10 = d10 * scale, s11 = d11 * scale;
                float m = fmaxf(s10, s11);
                float e0 = expf(s10 - m), e1 = expf(s11 - m);
                float inv = 1.f / (e0 + e1);
                if (lane == 0) { sc[0] = e0; sc[1] = e1; sc[2] = inv; }
                if ((b & 7) == 0) {
                    float4 v0 = ldcg4(g_qkv + 4096 + hh * HD + 4 * lane);
                    float4 v1 = ldcg4(g_qkv + 4096 + DIM + hh * HD + 4 * lane);
                    float* kv = kvc + (size_t)l * 4096;
                    ((float4*)(kv + hh * 256))[lane] = k0;
                    ((float4*)(kv + hh * 256 + HD))[lane] = k1;
                    ((float4*)(kv + 2048 + hh * 256))[lane] = v0;
                    ((float4*)(kv + 2048 + hh * 256 + HD))[lane] = v1;
                }
            }
            CBAR();
            if (tid < 16) {
                int dim = b * 16 + tid;
                float v0 = ldcg(&g_qkv[4096 + dim]);
                float v1 = ldcg(&g_qkv[4096 + DIM + dim]);
                xs2[tid] = make_float2(v0, (sc[0] * v0 + sc[1] * v1) * sc[2]);
            }
            CBAR();
            float a00 = 0.f, a01 = 0.f, a10 = 0.f, a11 = 0.f;
            CONSUME_BEGIN(4)
                const float2* bw = (const float2*)buf;
#pragma unroll
                for (int r = 0; r < 4; r++) {
                    float2 w = bw[r * CTHR + tid];
                    float2 x = xs2[_i * 4 + r];
                    a00 = fmaf(w.x, x.x, a00); a01 = fmaf(w.y, x.x, a01);
                    a10 = fmaf(w.x, x.y, a10); a11 = fmaf(w.y, x.y, a11);
                }
            CONSUME_END
            red2(g_h + 2 * tid, a00, a01);
            red2(g_h + DIM + 2 * tid, a10, a11);
        }
        gbar(2 + 4 * l);

        // ===== GATEUP =====
        if (b < 128) {
            int mat = b >> 6, rch = b & 63;
            float s0 = 0.f, s1 = 0.f;
#pragma unroll
            for (int i = 0; i < 2; i++) {
                int idx = tid + i * CTHR;
                float a = ldcg(&g_h[idx]), c = ldcg(&g_h[DIM + idx]);
                s0 += a * a; s1 += c * c;
            }
            s0 = bred512(s0, sbuf);
            s1 = bred512(s1, sbuf);
            float r0 = rsqrtf(s0 * (1.f / DIM) + EPSF);
            float r1 = rsqrtf(s1 * (1.f / DIM) + EPSF);
            if (tid < 16) {
                int idx = rch * 16 + tid;
                float wl = ln2[l * DIM + idx];
                xs2[tid] = make_float2(ldcg(&g_h[idx]) * r0 * wl,
                                       ldcg(&g_h[DIM + idx]) * r1 * wl);
            }
            CBAR();
            float4 A00 = {0,0,0,0}, A01 = {0,0,0,0}, A10 = {0,0,0,0}, A11 = {0,0,0,0};
            CONSUME_BEGIN(16)
                const float4* b4 = (const float4*)buf;
                float2 x = xs2[_i];
                float4 w0 = b4[tid];
                float4 w1 = b4[CTHR + tid];
                A00.x = fmaf(w0.x, x.x, A00.x); A00.y = fmaf(w0.y, x.x, A00.y);
                A00.z = fmaf(w0.z, x.x, A00.z); A00.w = fmaf(w0.w, x.x, A00.w);
                A10.x = fmaf(w0.x, x.y, A10.x); A10.y = fmaf(w0.y, x.y, A10.y);
                A10.z = fmaf(w0.z, x.y, A10.z); A10.w = fmaf(w0.w, x.y, A10.w);
                A01.x = fmaf(w1.x, x.x, A01.x); A01.y = fmaf(w1.y, x.x, A01.y);
                A01.z = fmaf(w1.z, x.x, A01.z); A01.w = fmaf(w1.w, x.x, A01.w);
                A11.x = fmaf(w1.x, x.y, A11.x); A11.y = fmaf(w1.y, x.y, A11.y);
                A11.z = fmaf(w1.z, x.y, A11.z); A11.w = fmaf(w1.w, x.y, A11.w);
            CONSUME_END
            float* o = g_gu + mat * 8192;
            red4(o + 4 * tid, A00);
            red4(o + 2048 + 4 * tid, A01);
            red4(o + FF + 4 * tid, A10);
            red4(o + FF + 2048 + 4 * tid, A11);
        }
        gbar(3 + 4 * l);

        // ===== DOWN =====
        if (b < 128) {
            if (tid < 32) {
                int idx = b * 32 + tid;
                float g0 = ldcg(&g_gu[idx]),        g1 = ldcg(&g_gu[FF + idx]);
                float u0 = ldcg(&g_gu[8192 + idx]), u1 = ldcg(&g_gu[8192 + FF + idx]);
                xs2[tid] = make_float2(g0 / (1.f + expf(-g0)) * u0,
                                       g1 / (1.f + expf(-g1)) * u1);
            }
            CBAR();
            float a00 = 0.f, a01 = 0.f, a10 = 0.f, a11 = 0.f;
            CONSUME_BEGIN(8)
                const float2* bw = (const float2*)buf;
#pragma unroll
                for (int r = 0; r < 4; r++) {
                    float2 w = bw[r * CTHR + tid];
                    float2 x = xs2[_i * 4 + r];
                    a00 = fmaf(w.x, x.x, a00); a01 = fmaf(w.y, x.x, a01);
                    a10 = fmaf(w.x, x.y, a10); a11 = fmaf(w.y, x.y, a11);
                }
            CONSUME_END
            red2(g_h + 2 * tid, a00, a01);
            red2(g_h + DIM + 2 * tid, a10, a11);
        }
        if (b < 12) g_qkv[b * CTHR + tid] = 0.f;   // zero next layer's qkv
        gbar(4 + 4 * l);
    }

    // ===== LM =====
    {
        float s = 0.f;
#pragma unroll
        for (int i = 0; i < 2; i++) {
            float v = ldcg(&g_h[DIM + tid + i * CTHR]);
            s += v * v;
        }
        s = bred512(s, sbuf);
        float r = rsqrtf(s * (1.f / DIM) + EPSF);
#pragma unroll
        for (int i = 0; i < 2; i++) {
            int idx = tid + i * CTHR;
            xsf[idx] = ldcg(&g_h[DIM + idx]) * r * fn[idx];
        }
        CBAR();

        float4 A = {0, 0, 0, 0};
        int curmat = -1;
        for (int c = c0; c < c1; c++) {
            int mat = c >> 6;
            if (mat != curmat) {
                if (curmat >= 0)
                    red4(logits + (size_t)curmat * VOC + 4 * tid, A);
                A = make_float4(0.f, 0.f, 0.f, 0.f);
                curmat = mat;
            }
            int rbase0 = (c & 63) * 16;
            CONSUME_BEGIN(8)
                const float4* b4 = (const float4*)buf;
#pragma unroll
                for (int r = 0; r < 2; r++) {
                    float x = xsf[rbase0 + _i * 2 + r];
                    float4 w = b4[r * CTHR + tid];
                    A.x = fmaf(w.x, x, A.x); A.y = fmaf(w.y, x, A.y);
                    A.z = fmaf(w.z, x, A.z); A.w = fmaf(w.w, x, A.w);
                }
            CONSUME_END
        }
        if (curmat >= 0) red4(logits + (size_t)curmat * VOC + 4 * tid, A);
    }

    // ===== restore barrier state for next graph replay =====
    CBAR();
    if (tid == 0) {
        unsigned old = atomicAdd(&g_fin, 1u);
        if (old == (unsigned)(NBLK - 1)) {
            for (int i = 0; i < 21; i++) g_bar[i] = 0u;
            __threadfence();
            g_fin = 0u;
        }
    }
}

// ---------------- host launcher ----------------
extern "C" void kernel_launch(void* const* d_in, const int* in_sizes, int n_in,
                              void* d_out, int out_size) {
    const float *past, *emb, *Wq, *Wk, *Wv, *Wo, *qn, *kn, *ln1, *ln2, *Wg, *Wu,
        *Wd, *fn, *lm;
    const int* tok;
    if (in_sizes[1] == 1) {
        past = (const float*)d_in[0];
        tok  = (const int*)d_in[1];
        emb  = (const float*)d_in[2];
        Wq = (const float*)d_in[3];  Wk = (const float*)d_in[4];
        Wv = (const float*)d_in[5];  Wo = (const float*)d_in[6];
        qn = (const float*)d_in[7];  kn = (const float*)d_in[8];
        ln1 = (const float*)d_in[9]; ln2 = (const float*)d_in[10];
        Wg = (const float*)d_in[11]; Wu = (const float*)d_in[12];
        Wd = (const float*)d_in[13]; fn = (const float*)d_in[14];
        lm = (const float*)d_in[15];
    } else {
        past = (const float*)d_in[0];
        emb  = (const float*)d_in[1];
        Wq = (const float*)d_in[2];  Wk = (const float*)d_in[3];
        Wv = (const float*)d_in[4];  Wo = (const float*)d_in[5];
        qn = (const float*)d_in[6];  kn = (const float*)d_in[7];
        ln1 = (const float*)d_in[8]; ln2 = (const float*)d_in[9];
        Wg = (const float*)d_in[10]; Wu = (const float*)d_in[11];
        Wd = (const float*)d_in[12]; fn = (const float*)d_in[13];
        lm = (const float*)d_in[14];
        tok = (const int*)d_in[15];
    }

    static bool attr_done = false;
    if (!attr_done) {
        cudaFuncSetAttribute(k_mega, cudaFuncAttributeMaxDynamicSharedMemorySize,
                             SM_TOTAL);
        attr_done = true;
    }

    float* out = (float*)d_out;
    float* logits = out;             // [15][2048]
    float* kvc = out + NLM * VOC;    // [10][8][2][128]

    k_mega<<<NBLK, NTHR, SM_TOTAL>>>(past, emb, tok, Wq, Wk, Wv, Wo, qn, kn,
                                     ln1, ln2, Wg, Wu, Wd, fn, lm, logits, kvc);
    (void)n_in; (void)out_size;
}